// round 6
// baseline (speedup 1.0000x reference)
#include <cuda_runtime.h>
#include <cstdint>

// ---------------------------------------------------------------------------
// Windowed XCA attention, fp32. B=4, C=192, H=W=224, WS=7 -> nW=4096 windows.
//   T: transpose w_qkv / w_proj into K-major scratch (tiny)
//   A: QKV dense GEMM  (cp.async 3-stage, 3 CTAs/SM)   -> g_qkv (planar)
//   C: per (window,head): dwconv3x3 + norms + KtQ + softmax + V*attn (f32x2)
//   D: proj dense GEMM  (same template)                -> out (planar)
// ---------------------------------------------------------------------------

#define BATCH 4
#define CH    192
#define IMG   224
#define HW    50176
#define HEADS 6
#define HC    32
#define NW    4096
#define OQ    576
#define NPIX  49
#define CSTR  52

typedef unsigned long long ull;

__device__ float g_qkv [(size_t)BATCH * OQ * HW];    // 462 MB
__device__ float g_attn[(size_t)BATCH * CH * HW];    // 154 MB
__device__ float g_wt[(OQ + CH) * CH];               // transposed weights

__device__ __forceinline__ ull pack2(float lo, float hi) {
    ull r; asm("mov.b64 %0, {%1, %2};" : "=l"(r) : "f"(lo), "f"(hi)); return r;
}
__device__ __forceinline__ void unpack2(ull v, float& lo, float& hi) {
    asm("mov.b64 {%0, %1}, %2;" : "=f"(lo), "=f"(hi) : "l"(v));
}
__device__ __forceinline__ ull fma2(ull a, ull b, ull c) {
    ull d; asm("fma.rn.f32x2 %0, %1, %2, %3;" : "=l"(d) : "l"(a), "l"(b), "l"(c)); return d;
}
__device__ __forceinline__ void cp16(void* dst, const void* src) {
    unsigned d = (unsigned)__cvta_generic_to_shared(dst);
    asm volatile("cp.async.cg.shared.global [%0], [%1], 16;" :: "r"(d), "l"(src));
}

// ---------------------------------------------------------------------------
// T: transpose weights: g_wt[off + c*M + o] = src[o*CH + c]
// ---------------------------------------------------------------------------
__global__ void transpose_w(const float* __restrict__ src, int M, int off)
{
    const int i = blockIdx.x * 256 + threadIdx.x;
    if (i < M * CH) {
        const int o = i / CH, c = i % CH;
        g_wt[off + c * M + o] = src[i];
    }
}

// ---------------------------------------------------------------------------
// A/D: 1x1 conv dense GEMM, cp.async 3-stage pipeline.
// Block tile 96(M) x 128(N), BK=16, 192 threads, thread tile 8x8 (f32x2).
// MODE 0: in = x param, out = g_qkv, wt at g_wt[0], MT=576.
// MODE 1: in = g_attn,  out = param, wt at g_wt[OQ*CH], MT=192.
// ---------------------------------------------------------------------------
#define BM 96
#define BN 128
#define BK 16
#define KITERS (CH / BK)   // 12

template<int MT, int MODE>
__global__ __launch_bounds__(192, 3)
void conv1x1_kernel(const float* __restrict__ in_p,
                    const float* __restrict__ bias,
                    float* __restrict__ out_p)
{
    __shared__ __align__(16) float a_s[3][BK][100];   // K-major weight tile
    __shared__ __align__(16) float b_s[3][BK][BN];    // input pixel tile

    const float* in = (MODE == 0) ? in_p : (const float*)g_attn;
    float* out      = (MODE == 0) ? (float*)g_qkv : out_p;
    const float* wt = g_wt + (MODE == 0 ? 0 : OQ * CH);

    const int t  = threadIdx.x;
    const int n0 = blockIdx.x * BN;
    const int m0 = blockIdx.y * BM;
    const int b  = blockIdx.z;

    const float* inb = in + (size_t)b * CH * HW + n0;
    const float* wtb = wt + m0;                   // row stride MT
    float* outb = out + ((size_t)b * MT + m0) * HW + n0;

    const int tx = t & 15;
    const int ty = t >> 4;
    const int pn = tx * 8;
    const int om = ty * 8;

    // cp.async chunk mapping
    const int b_r0 = t >> 5, b_c0 = (t & 31) * 4;     // rows +0,+6,+12
    const int a_r0 = t / 24, a_c0 = (t % 24) * 4;     // rows +0,+8

    auto issue = [&](int it, int s) {
        const int kb = it * BK;
        cp16(&b_s[s][b_r0][b_c0],      inb + (size_t)(kb + b_r0)      * HW + b_c0);
        cp16(&b_s[s][b_r0 + 6][b_c0],  inb + (size_t)(kb + b_r0 + 6)  * HW + b_c0);
        if (t < 128)
            cp16(&b_s[s][b_r0 + 12][b_c0], inb + (size_t)(kb + b_r0 + 12) * HW + b_c0);
        cp16(&a_s[s][a_r0][a_c0],      wtb + (size_t)(kb + a_r0)      * MT + a_c0);
        cp16(&a_s[s][a_r0 + 8][a_c0],  wtb + (size_t)(kb + a_r0 + 8)  * MT + a_c0);
        asm volatile("cp.async.commit_group;");
    };

    issue(0, 0);
    issue(1, 1);

    ull acc[8][4];
#pragma unroll
    for (int i = 0; i < 8; ++i)
#pragma unroll
        for (int p = 0; p < 4; ++p) acc[i][p] = 0ULL;

    for (int it = 0; it < KITERS; ++it) {
        if (it < KITERS - 1) asm volatile("cp.async.wait_group 1;");
        else                 asm volatile("cp.async.wait_group 0;");
        __syncthreads();
        if (it + 2 < KITERS) issue(it + 2, (it + 2) % 3);

        const int s = it % 3;
#pragma unroll
        for (int kk = 0; kk < BK; ++kk) {
            const float4 wa = *(const float4*)&a_s[s][kk][om];
            const float4 wc = *(const float4*)&a_s[s][kk][om + 4];
            const float4 xa = *(const float4*)&b_s[s][kk][pn];
            const float4 xb = *(const float4*)&b_s[s][kk][pn + 4];
            ull xp[4];
            xp[0] = pack2(xa.x, xa.y); xp[1] = pack2(xa.z, xa.w);
            xp[2] = pack2(xb.x, xb.y); xp[3] = pack2(xb.z, xb.w);
            const float av[8] = {wa.x, wa.y, wa.z, wa.w, wc.x, wc.y, wc.z, wc.w};
#pragma unroll
            for (int i = 0; i < 8; ++i) {
                const ull wp = pack2(av[i], av[i]);
#pragma unroll
                for (int p = 0; p < 4; ++p) acc[i][p] = fma2(wp, xp[p], acc[i][p]);
            }
        }
    }

#pragma unroll
    for (int i = 0; i < 8; ++i) {
        const int o = om + i;
        const float bb = bias[m0 + o];
        float r0, r1, r2, r3;
        unpack2(acc[i][0], r0, r1); unpack2(acc[i][1], r2, r3);
        *(float4*)(outb + (size_t)o * HW + pn) =
            make_float4(r0 + bb, r1 + bb, r2 + bb, r3 + bb);
        unpack2(acc[i][2], r0, r1); unpack2(acc[i][3], r2, r3);
        *(float4*)(outb + (size_t)o * HW + pn + 4) =
            make_float4(r0 + bb, r1 + bb, r2 + bb, r3 + bb);
    }
}

// ---------------------------------------------------------------------------
// C: attention per (window, head). grid (NW, HEADS), 192 thr, ~31 KB smem.
// at matrix stored [m][n] (transposed) -> contiguous softmax + vector V*attn.
// ---------------------------------------------------------------------------
__global__ __launch_bounds__(192)
void attn_kernel(const float* __restrict__ w_dw,
                 const float* __restrict__ b_dw,
                 const float* __restrict__ temperature)
{
    __shared__ __align__(16) float s_qkv[96 * CSTR];   // q:0..31 k:32..63 v:64..95
    __shared__ __align__(16) float at[NPIX * CSTR];    // [m][n]
    __shared__ float invq[CSTR], invk[CSTR];
    __shared__ int   lut[NPIX];

    const int win = blockIdx.x;
    const int h   = blockIdx.y;
    const int t   = threadIdx.x;
    const int b  = win >> 10;
    const int wh = (win >> 5) & 31;
    const int ww = win & 31;

    float* q_s = s_qkv;
    float* k_s = s_qkv + 32 * CSTR;
    float* v_s = s_qkv + 64 * CSTR;

    if (t < NPIX) lut[t] = (t / 7) * IMG + (t % 7);
    __syncthreads();

    // ---- phase 0: coalesced divmod-free load of 96ch x 49px slab ----
    {
        const size_t gbase = (size_t)b * OQ * HW + (size_t)(wh * 7) * IMG + ww * 7;
        int c = t / NPIX;
        int p = t % NPIX;
#pragma unroll
        for (int itr = 0; itr < 25; ++itr) {
            if (c < 96) {
                const int ch = c + ((c >> 5) * 160) + h * HC;
                s_qkv[c * CSTR + p] = __ldg(&g_qkv[gbase + (size_t)ch * HW + lut[p]]);
            }
            c += 3; p += 45;
            if (p >= NPIX) { p -= NPIX; c += 1; }
        }
    }
    __syncthreads();

    // ---- phase 1: dwconv 3x3 in place (window zero-padded) ----
    {
        const int c    = t >> 1;          // 0..95
        const int half = t & 1;
        const int ch   = (c >> 5) * CH + h * HC + (c & 31);
        float* row0 = s_qkv + c * CSTR;

        float w9[9];
#pragma unroll
        for (int k = 0; k < 9; ++k) w9[k] = w_dw[ch * 9 + k];
        const float bb = b_dw[ch];

        float in[5][7];
        const int r0 = half ? 3 : 0;
        const int nr = half ? 4 : 5;
        for (int r = 0; r < nr; ++r)
#pragma unroll
            for (int j = 0; j < 7; ++j) in[r][j] = row0[(r0 + r) * 7 + j];
        __syncthreads();   // all reads done before in-place writes

        if (!half) {
#pragma unroll
            for (int i = 0; i < 4; ++i) {
#pragma unroll
                for (int j = 0; j < 7; ++j) {
                    float s = bb;
#pragma unroll
                    for (int di = -1; di <= 1; ++di) {
                        const int ii = i + di;
                        if (ii < 0) continue;
#pragma unroll
                        for (int dj = -1; dj <= 1; ++dj) {
                            const int jj = j + dj;
                            if (jj >= 0 && jj < 7)
                                s += w9[(di + 1) * 3 + (dj + 1)] * in[ii][jj];
                        }
                    }
                    row0[i * 7 + j] = s;
                }
            }
        } else {
#pragma unroll
            for (int i = 4; i < 7; ++i) {
#pragma unroll
                for (int j = 0; j < 7; ++j) {
                    float s = bb;
#pragma unroll
                    for (int di = -1; di <= 1; ++di) {
                        const int ii = i + di;
                        if (ii > 6) continue;
#pragma unroll
                        for (int dj = -1; dj <= 1; ++dj) {
                            const int jj = j + dj;
                            if (jj >= 0 && jj < 7)
                                s += w9[(di + 1) * 3 + (dj + 1)] * in[ii - 3][jj];
                        }
                    }
                    row0[i * 7 + j] = s;
                }
            }
        }
    }
    __syncthreads();

    // ---- phase 2: inverse norms (temperature folded into q side) ----
    if (t < 2 * NPIX) {
        const int part = t / NPIX, p = t % NPIX;
        const float* s = s_qkv + part * 32 * CSTR;
        float acc = 0.f;
#pragma unroll
        for (int c = 0; c < HC; ++c) { const float v = s[c * CSTR + p]; acc += v * v; }
        const float nm = fmaxf(sqrtf(acc), 1e-12f);
        if (part == 0) invq[p] = temperature[h] / nm;
        else           invk[p] = 1.f / nm;
    }
    __syncthreads();

    // ---- phase 3: at[m][n] = (sum_c k[c][n]*q[c][m]) * invk[n]*invq[m] ----
    if (t < 175) {
        const int n0 = 2 * (t / 7), m0 = 7 * (t % 7);   // n0 pair, 7 m's
        ull acc2[7];
#pragma unroll
        for (int jm = 0; jm < 7; ++jm) acc2[jm] = 0ULL;
#pragma unroll
        for (int c = 0; c < HC; ++c) {
            const ull kp = *(const ull*)&k_s[c * CSTR + n0];   // 8B aligned
#pragma unroll
            for (int jm = 0; jm < 7; ++jm) {
                const float qv = q_s[c * CSTR + m0 + jm];
                acc2[jm] = fma2(pack2(qv, qv), kp, acc2[jm]);
            }
        }
        const float ik0 = invk[n0];
        const float ik1 = invk[n0 + 1];   // n0=48: pad value, result discarded
#pragma unroll
        for (int jm = 0; jm < 7; ++jm) {
            float s0, s1; unpack2(acc2[jm], s0, s1);
            const float iq = invq[m0 + jm];
            *(float2*)&at[(m0 + jm) * CSTR + n0] = make_float2(s0 * ik0 * iq, s1 * ik1 * iq);
        }
    }
    __syncthreads();

    // ---- phase 4: softmax over n per row m (contiguous; 2 threads/row) ----
    {
        const int m = (t < 98) ? (t >> 1) : 0;   // dummies track row 0
        const int part = t & 1;
        const float* row = &at[m * CSTR];
        const int nb = part ? 25 : 0, ne = part ? NPIX : 25;
        float mx = -1e30f;
        for (int n = nb; n < ne; ++n) mx = fmaxf(mx, row[n]);
        mx = fmaxf(mx, __shfl_xor_sync(0xffffffffu, mx, 1));
        float ev[25];
        float ssum = 0.f;
        int cnt = 0;
        for (int n = nb; n < ne; ++n) {
            const float e = __expf(row[n] - mx);
            ev[cnt++] = e;
            ssum += e;
        }
        ssum += __shfl_xor_sync(0xffffffffu, ssum, 1);
        const float r = 1.f / ssum;
        __syncthreads();   // all reads of at done before stores
        if (t < 98) {
            cnt = 0;
            for (int n = nb; n < ne; ++n) at[m * CSTR + n] = ev[cnt++] * r;
        }
    }
    __syncthreads();

    // ---- phase 5: out[c][m] = sum_n v[c][n]*at[m][n] (vector row dots) ----
    for (int u = t; u < HC * 7; u += 192) {      // 224 units: (channel, window-row)
        const int c = u / 7, mg = u % 7;
        const int m0 = 7 * mg;
        const float* vr = &v_s[c * CSTR];
        ull acc2[7];
#pragma unroll
        for (int jm = 0; jm < 7; ++jm) acc2[jm] = 0ULL;
#pragma unroll
        for (int n = 0; n < 48; n += 4) {
            const ulonglong2 vv = *(const ulonglong2*)&vr[n];
#pragma unroll
            for (int jm = 0; jm < 7; ++jm) {
                const ulonglong2 aa = *(const ulonglong2*)&at[(m0 + jm) * CSTR + n];
                acc2[jm] = fma2(vv.x, aa.x, acc2[jm]);
                acc2[jm] = fma2(vv.y, aa.y, acc2[jm]);
            }
        }
        const float v48 = vr[48];
        float* dst = g_attn + (((size_t)(b * CH + h * HC + c) * IMG) + wh * 7 + mg) * IMG + ww * 7;
#pragma unroll
        for (int jm = 0; jm < 7; ++jm) {
            float lo, hi; unpack2(acc2[jm], lo, hi);
            dst[jm] = lo + hi + v48 * at[(m0 + jm) * CSTR + 48];
        }
    }
}

// ---------------------------------------------------------------------------
extern "C" void kernel_launch(void* const* d_in, const int* in_sizes, int n_in,
                              void* d_out, int out_size)
{
    const float* x      = (const float*)d_in[0];
    const float* w_qkv  = (const float*)d_in[1];
    const float* b_qkv  = (const float*)d_in[2];
    const float* w_dw   = (const float*)d_in[3];
    const float* b_dw   = (const float*)d_in[4];
    const float* w_proj = (const float*)d_in[5];
    const float* b_proj = (const float*)d_in[6];
    const float* temp   = (const float*)d_in[7];
    float* out = (float*)d_out;

    // T: transpose weights into K-major scratch
    transpose_w<<<(OQ * CH + 255) / 256, 256>>>(w_qkv, OQ, 0);
    transpose_w<<<(CH * CH + 255) / 256, 256>>>(w_proj, CH, OQ * CH);
    // A: QKV GEMM -> g_qkv
    conv1x1_kernel<OQ, 0><<<dim3(HW / BN, OQ / BM, BATCH), 192>>>(x, b_qkv, nullptr);
    // C: fused dwconv + attention -> g_attn
    attn_kernel<<<dim3(NW, HEADS), 192>>>(w_dw, b_dw, temp);
    // D: proj GEMM -> out
    conv1x1_kernel<CH, 1><<<dim3(HW / BN, CH / BM, BATCH), 192>>>(nullptr, b_proj, out);
}

// round 7
// speedup vs baseline: 1.0243x; 1.0243x over previous
#include <cuda_runtime.h>
#include <cstdint>

// ---------------------------------------------------------------------------
// Windowed XCA attention, fp32. B=4, C=192, H=W=224, WS=7 -> nW=4096 windows.
//   T: transpose w_qkv / w_proj into K-major scratch (tiny)
//   A: QKV dense GEMM  (cp.async 3-stage, 8x14 tile)   -> g_qkv (planar)
//   C: per (window,head): dwconv3x3 + norms + KtQ + softmax + V*attn
//      (round-5 proven version)
//   D: proj dense GEMM  (same template)                -> out (planar)
// ---------------------------------------------------------------------------

#define BATCH 4
#define CH    192
#define IMG   224
#define HW    50176
#define HEADS 6
#define HC    32
#define NW    4096
#define OQ    576
#define NPIX  49
#define CSTR  50

typedef unsigned long long ull;

__device__ float g_qkv [(size_t)BATCH * OQ * HW];    // 462 MB
__device__ float g_attn[(size_t)BATCH * CH * HW];    // 154 MB
__device__ float g_wt[(OQ + CH) * CH];               // transposed weights

__device__ __forceinline__ ull pack2(float lo, float hi) {
    ull r; asm("mov.b64 %0, {%1, %2};" : "=l"(r) : "f"(lo), "f"(hi)); return r;
}
__device__ __forceinline__ void unpack2(ull v, float& lo, float& hi) {
    asm("mov.b64 {%0, %1}, %2;" : "=f"(lo), "=f"(hi) : "l"(v));
}
__device__ __forceinline__ ull fma2(ull a, ull b, ull c) {
    ull d; asm("fma.rn.f32x2 %0, %1, %2, %3;" : "=l"(d) : "l"(a), "l"(b), "l"(c)); return d;
}
__device__ __forceinline__ void cp16(void* dst, const void* src) {
    unsigned d = (unsigned)__cvta_generic_to_shared(dst);
    asm volatile("cp.async.cg.shared.global [%0], [%1], 16;" :: "r"(d), "l"(src));
}

// ---------------------------------------------------------------------------
// T: transpose weights: g_wt[off + c*M + o] = src[o*CH + c]
// ---------------------------------------------------------------------------
__global__ void transpose_w(const float* __restrict__ src, int M, int off)
{
    const int i = blockIdx.x * 256 + threadIdx.x;
    if (i < M * CH) {
        const int o = i / CH, c = i % CH;
        g_wt[off + c * M + o] = src[i];
    }
}

// ---------------------------------------------------------------------------
// A/D: 1x1 conv dense GEMM, cp.async 3-stage, thread tile 8(M) x 14(N).
// Block tile 96(M) x 224(N), BK=16, 192 threads (12 ty x 16 tx).
// MODE 0: in = x param, out = g_qkv, wt at g_wt[0], MT=576.
// MODE 1: in = g_attn,  out = param, wt at g_wt[OQ*CH], MT=192.
// ---------------------------------------------------------------------------
#define BM 96
#define BN 224
#define BK 16
#define KITERS (CH / BK)   // 12
#define BF4 ((BK * BN) / 4)  // 896 float4 per b stage
#define AF4 ((BK * BM) / 4)  // 384 float4 per a stage

template<int MT, int MODE>
__global__ __launch_bounds__(192, 2)
void conv1x1_kernel(const float* __restrict__ in_p,
                    const float* __restrict__ bias,
                    float* __restrict__ out_p)
{
    __shared__ __align__(16) float a_s[3][BK][100];   // K-major weight tile
    __shared__ __align__(16) float b_s[3][BK][BN];    // input pixel tile

    const float* in = (MODE == 0) ? in_p : (const float*)g_attn;
    float* out      = (MODE == 0) ? (float*)g_qkv : out_p;
    const float* wt = g_wt + (MODE == 0 ? 0 : OQ * CH);

    const int t  = threadIdx.x;
    const int n0 = blockIdx.x * BN;
    const int m0 = blockIdx.y * BM;
    const int b  = blockIdx.z;

    const float* inb = in + (size_t)b * CH * HW + n0;
    const float* wtb = wt + m0;                   // row stride MT
    float* outb = out + ((size_t)b * MT + m0) * HW + n0;

    const int tx = t & 15;
    const int ty = t >> 4;
    const int pn = tx * 14;
    const int om = ty * 8;

    // cp.async chunk mapping (precomputed; BN=224 -> divmod by 56)
    int b_r[5], b_c[5];
#pragma unroll
    for (int i = 0; i < 5; ++i) {
        const int u = t + i * 192;
        b_r[i] = u / 56;
        b_c[i] = (u % 56) * 4;
    }
    const bool b_has4 = (t + 4 * 192) < BF4;   // 896 = 4*192 + 128
    int a_r[2], a_c[2];
#pragma unroll
    for (int i = 0; i < 2; ++i) {
        const int u = t + i * 192;
        a_r[i] = u / 24;
        a_c[i] = (u % 24) * 4;
    }

    auto issue = [&](int it, int s) {
        const int kb = it * BK;
#pragma unroll
        for (int i = 0; i < 4; ++i)
            cp16(&b_s[s][b_r[i]][b_c[i]], inb + (size_t)(kb + b_r[i]) * HW + b_c[i]);
        if (b_has4)
            cp16(&b_s[s][b_r[4]][b_c[4]], inb + (size_t)(kb + b_r[4]) * HW + b_c[4]);
#pragma unroll
        for (int i = 0; i < 2; ++i)
            cp16(&a_s[s][a_r[i]][a_c[i]], wtb + (size_t)(kb + a_r[i]) * MT + a_c[i]);
        asm volatile("cp.async.commit_group;");
    };

    issue(0, 0);
    issue(1, 1);

    ull acc[8][7];
#pragma unroll
    for (int i = 0; i < 8; ++i)
#pragma unroll
        for (int p = 0; p < 7; ++p) acc[i][p] = 0ULL;

    for (int it = 0; it < KITERS; ++it) {
        if (it < KITERS - 1) asm volatile("cp.async.wait_group 1;");
        else                 asm volatile("cp.async.wait_group 0;");
        __syncthreads();
        if (it + 2 < KITERS) issue(it + 2, (it + 2) % 3);

        const int s = it % 3;
#pragma unroll
        for (int kk = 0; kk < BK; ++kk) {
            const float4 wa = *(const float4*)&a_s[s][kk][om];
            const float4 wc = *(const float4*)&a_s[s][kk][om + 4];
            ull xp[7];
#pragma unroll
            for (int p = 0; p < 7; ++p)
                xp[p] = *(const ull*)&b_s[s][kk][pn + 2 * p];   // 8B aligned
            const float av[8] = {wa.x, wa.y, wa.z, wa.w, wc.x, wc.y, wc.z, wc.w};
#pragma unroll
            for (int i = 0; i < 8; ++i) {
                const ull wp = pack2(av[i], av[i]);
#pragma unroll
                for (int p = 0; p < 7; ++p) acc[i][p] = fma2(wp, xp[p], acc[i][p]);
            }
        }
    }

#pragma unroll
    for (int i = 0; i < 8; ++i) {
        const int o = om + i;
        const float bb = bias[m0 + o];
        float* orow = outb + (size_t)o * HW + pn;
#pragma unroll
        for (int p = 0; p < 7; ++p) {
            float lo, hi; unpack2(acc[i][p], lo, hi);
            *(float2*)(orow + 2 * p) = make_float2(lo + bb, hi + bb);
        }
    }
}

// ---------------------------------------------------------------------------
// C: attention per (window, head) — round-5 proven version.
// grid (NW, HEADS), 192 thr, ~30 KB smem.
// ---------------------------------------------------------------------------
__global__ __launch_bounds__(192)
void attn_kernel(const float* __restrict__ w_dw,
                 const float* __restrict__ b_dw,
                 const float* __restrict__ temperature)
{
    __shared__ float q_s[HC * CSTR];
    __shared__ float k_s[HC * CSTR];
    __shared__ float v_s[HC * CSTR];
    __shared__ float at [NPIX * CSTR];
    __shared__ float invq[NPIX], invk[NPIX];

    const int win = blockIdx.x;
    const int h   = blockIdx.y;
    const int t   = threadIdx.x;
    const int b  = win >> 10;
    const int wh = (win >> 5) & 31;
    const int ww = win & 31;

    // ---- phase 0: coalesced load (consecutive threads = consecutive pixels)
    {
        const size_t gbase = (size_t)b * OQ * HW + (size_t)(wh * 7) * IMG + ww * 7;
#pragma unroll
        for (int it = 0; it < 25; ++it) {
            const int u = t + it * 192;
            if (u < 96 * NPIX) {
                const int c = u / NPIX, p = u % NPIX;
                const int sel = c >> 5, cc = c & 31;
                const int ch = sel * CH + h * HC + cc;
                const float v = __ldg(&g_qkv[gbase + (size_t)ch * HW + (p / 7) * IMG + p % 7]);
                float* dstp = (sel == 0) ? q_s : (sel == 1) ? k_s : v_s;
                dstp[cc * CSTR + p] = v;
            }
        }
    }
    __syncthreads();

    // ---- phase 1: dwconv 3x3 in place (window zero-padded) ----
    {
        const int c    = t >> 1;          // 0..95
        const int half = t & 1;
        const int sel  = c >> 5;          // 0=q 1=k 2=v
        const int cc   = c & 31;
        const int ch   = sel * CH + h * HC + cc;
        float* dstp = (sel == 0) ? q_s : (sel == 1) ? k_s : v_s;
        float* row0 = dstp + cc * CSTR;

        float w9[9];
#pragma unroll
        for (int k = 0; k < 9; ++k) w9[k] = w_dw[ch * 9 + k];
        const float bb = b_dw[ch];

        float in[5][7];
        const int r0 = half ? 3 : 0;
        const int nr = half ? 4 : 5;
        for (int r = 0; r < nr; ++r)
#pragma unroll
            for (int j = 0; j < 7; ++j) in[r][j] = row0[(r0 + r) * 7 + j];
        __syncthreads();   // all reads done before in-place writes

        if (!half) {
#pragma unroll
            for (int i = 0; i < 4; ++i) {
#pragma unroll
                for (int j = 0; j < 7; ++j) {
                    float s = bb;
#pragma unroll
                    for (int di = -1; di <= 1; ++di) {
                        const int ii = i + di;
                        if (ii < 0) continue;
#pragma unroll
                        for (int dj = -1; dj <= 1; ++dj) {
                            const int jj = j + dj;
                            if (jj >= 0 && jj < 7)
                                s += w9[(di + 1) * 3 + (dj + 1)] * in[ii][jj];
                        }
                    }
                    row0[i * 7 + j] = s;
                }
            }
        } else {
#pragma unroll
            for (int i = 4; i < 7; ++i) {
#pragma unroll
                for (int j = 0; j < 7; ++j) {
                    float s = bb;
#pragma unroll
                    for (int di = -1; di <= 1; ++di) {
                        const int ii = i + di;
                        if (ii > 6) continue;
#pragma unroll
                        for (int dj = -1; dj <= 1; ++dj) {
                            const int jj = j + dj;
                            if (jj >= 0 && jj < 7)
                                s += w9[(di + 1) * 3 + (dj + 1)] * in[ii - 3][jj];
                        }
                    }
                    row0[i * 7 + j] = s;
                }
            }
        }
    }
    __syncthreads();

    // ---- phase 2: inverse norms (temperature folded into q side) ----
    if (t < 2 * NPIX) {
        const int part = t / NPIX, p = t % NPIX;
        const float* s = part ? k_s : q_s;
        float acc = 0.f;
#pragma unroll
        for (int c = 0; c < HC; ++c) { const float v = s[c * CSTR + p]; acc += v * v; }
        const float nm = fmaxf(sqrtf(acc), 1e-12f);
        if (part == 0) invq[p] = temperature[h] / nm;
        else           invk[p] = 1.f / nm;
    }
    __syncthreads();

    // ---- phase 3: attn[n][m] = (sum_c k[c][n]*q[c][m]) * invk[n]*invq[m] ----
    if (t < 175) {
        const int n0 = 2 * (t / 7), m0 = 7 * (t % 7);
        const bool hasN1 = (n0 + 1 < NPIX);
        float a0[7], a1[7];
#pragma unroll
        for (int jm = 0; jm < 7; ++jm) { a0[jm] = 0.f; a1[jm] = 0.f; }
#pragma unroll
        for (int c = 0; c < HC; ++c) {
            const float k0 = k_s[c * CSTR + n0];
            const float k1 = hasN1 ? k_s[c * CSTR + n0 + 1] : 0.f;
#pragma unroll
            for (int jm = 0; jm < 7; ++jm) {
                const float qv = q_s[c * CSTR + m0 + jm];
                a0[jm] += k0 * qv;
                a1[jm] += k1 * qv;
            }
        }
        const float ik0 = invk[n0];
#pragma unroll
        for (int jm = 0; jm < 7; ++jm)
            at[n0 * CSTR + m0 + jm] = a0[jm] * ik0 * invq[m0 + jm];
        if (hasN1) {
            const float ik1 = invk[n0 + 1];
#pragma unroll
            for (int jm = 0; jm < 7; ++jm)
                at[(n0 + 1) * CSTR + m0 + jm] = a1[jm] * ik1 * invq[m0 + jm];
        }
    }
    __syncthreads();

    // ---- phase 4: softmax over n per column m (2 threads/col + shfl) ----
    {
        const int m = (t < 98) ? (t >> 1) : 0;   // dummies track col 0
        const int part = t & 1;
        float mx = -1e30f;
        for (int n = part; n < NPIX; n += 2) mx = fmaxf(mx, at[n * CSTR + m]);
        mx = fmaxf(mx, __shfl_xor_sync(0xffffffffu, mx, 1));
        float ev[25];
        float ssum = 0.f;
        int cnt = 0;
        for (int n = part; n < NPIX; n += 2) {
            const float e = __expf(at[n * CSTR + m] - mx);
            ev[cnt++] = e;
            ssum += e;
        }
        ssum += __shfl_xor_sync(0xffffffffu, ssum, 1);
        const float r = 1.f / ssum;
        __syncthreads();   // all reads of at done before stores
        if (t < 98) {
            cnt = 0;
            for (int n = part; n < NPIX; n += 2) at[n * CSTR + m] = ev[cnt++] * r;
        }
    }
    __syncthreads();

    // ---- phase 5: out[c][m] = sum_n v[c][n]*attn[n][m], all 192 threads ----
    for (int u = t; u < HC * 7; u += 192) {      // 224 units: (channel, row-group)
        const int c = u / 7, mg = u % 7;
        const int m0 = 7 * mg;
        float a[7];
#pragma unroll
        for (int jm = 0; jm < 7; ++jm) a[jm] = 0.f;
        for (int n = 0; n < NPIX; ++n) {
            const float v0 = v_s[c * CSTR + n];
#pragma unroll
            for (int jm = 0; jm < 7; ++jm) a[jm] += v0 * at[n * CSTR + m0 + jm];
        }
        float* dst = g_attn + (((size_t)(b * CH + h * HC + c) * IMG) + wh * 7 + mg) * IMG + ww * 7;
#pragma unroll
        for (int jm = 0; jm < 7; ++jm) dst[jm] = a[jm];
    }
}

// ---------------------------------------------------------------------------
extern "C" void kernel_launch(void* const* d_in, const int* in_sizes, int n_in,
                              void* d_out, int out_size)
{
    const float* x      = (const float*)d_in[0];
    const float* w_qkv  = (const float*)d_in[1];
    const float* b_qkv  = (const float*)d_in[2];
    const float* w_dw   = (const float*)d_in[3];
    const float* b_dw   = (const float*)d_in[4];
    const float* w_proj = (const float*)d_in[5];
    const float* b_proj = (const float*)d_in[6];
    const float* temp   = (const float*)d_in[7];
    float* out = (float*)d_out;

    // T: transpose weights into K-major scratch
    transpose_w<<<(OQ * CH + 255) / 256, 256>>>(w_qkv, OQ, 0);
    transpose_w<<<(CH * CH + 255) / 256, 256>>>(w_proj, CH, OQ * CH);
    // A: QKV GEMM -> g_qkv
    conv1x1_kernel<OQ, 0><<<dim3(HW / BN, OQ / BM, BATCH), 192>>>(x, b_qkv, nullptr);
    // C: fused dwconv + attention -> g_attn
    attn_kernel<<<dim3(NW, HEADS), 192>>>(w_dw, b_dw, temp);
    // D: proj GEMM -> out
    conv1x1_kernel<CH, 1><<<dim3(HW / BN, CH / BM, BATCH), 192>>>(nullptr, b_proj, out);
}

// round 8
// speedup vs baseline: 1.1003x; 1.0741x over previous
#include <cuda_runtime.h>
#include <cstdint>

// ---------------------------------------------------------------------------
// Windowed XCA attention, fp32. B=4, C=192, H=W=224, WS=7 -> nW=4096 windows.
//   T: transpose w_qkv / w_proj into K-major scratch (tiny)
//   A: QKV dense GEMM  (cp.async 3-stage, 8x8 tile, 3 CTA/SM) -> g_qkv
//   C: per (window,head): dwconv3x3 + norms + KtQ + softmax + V*attn
//   D: proj dense GEMM  (same template)                       -> out
// ---------------------------------------------------------------------------

#define BATCH 4
#define CH    192
#define IMG   224
#define HW    50176
#define HEADS 6
#define HC    32
#define NW    4096
#define OQ    576
#define NPIX  49
#define CSTR  50

typedef unsigned long long ull;

__device__ float g_qkv [(size_t)BATCH * OQ * HW];    // 462 MB
__device__ float g_attn[(size_t)BATCH * CH * HW];    // 154 MB
__device__ float g_wt[(OQ + CH) * CH];               // transposed weights

__device__ __forceinline__ ull pack2(float lo, float hi) {
    ull r; asm("mov.b64 %0, {%1, %2};" : "=l"(r) : "f"(lo), "f"(hi)); return r;
}
__device__ __forceinline__ void unpack2(ull v, float& lo, float& hi) {
    asm("mov.b64 {%0, %1}, %2;" : "=f"(lo), "=f"(hi) : "l"(v));
}
__device__ __forceinline__ ull fma2(ull a, ull b, ull c) {
    ull d; asm("fma.rn.f32x2 %0, %1, %2, %3;" : "=l"(d) : "l"(a), "l"(b), "l"(c)); return d;
}
__device__ __forceinline__ void cp16(void* dst, const void* src) {
    unsigned d = (unsigned)__cvta_generic_to_shared(dst);
    asm volatile("cp.async.cg.shared.global [%0], [%1], 16;" :: "r"(d), "l"(src));
}

// ---------------------------------------------------------------------------
// T: transpose weights: g_wt[off + c*M + o] = src[o*CH + c]
// ---------------------------------------------------------------------------
__global__ void transpose_w(const float* __restrict__ src, int M, int off)
{
    const int i = blockIdx.x * 256 + threadIdx.x;
    if (i < M * CH) {
        const int o = i / CH, c = i % CH;
        g_wt[off + c * M + o] = src[i];
    }
}

// ---------------------------------------------------------------------------
// A/D: 1x1 conv dense GEMM, cp.async 3-stage pipeline (round-6 proven).
// Block tile 96(M) x 128(N), BK=16, 192 threads, thread tile 8x8 (f32x2).
// ---------------------------------------------------------------------------
#define BM 96
#define BN 128
#define BK 16
#define KITERS (CH / BK)   // 12

template<int MT, int MODE>
__global__ __launch_bounds__(192, 3)
void conv1x1_kernel(const float* __restrict__ in_p,
                    const float* __restrict__ bias,
                    float* __restrict__ out_p)
{
    __shared__ __align__(16) float a_s[3][BK][100];   // K-major weight tile
    __shared__ __align__(16) float b_s[3][BK][BN];    // input pixel tile

    const float* in = (MODE == 0) ? in_p : (const float*)g_attn;
    float* out      = (MODE == 0) ? (float*)g_qkv : out_p;
    const float* wt = g_wt + (MODE == 0 ? 0 : OQ * CH);

    const int t  = threadIdx.x;
    const int n0 = blockIdx.x * BN;
    const int m0 = blockIdx.y * BM;
    const int b  = blockIdx.z;

    const float* inb = in + (size_t)b * CH * HW + n0;
    const float* wtb = wt + m0;                   // row stride MT
    float* outb = out + ((size_t)b * MT + m0) * HW + n0;

    const int tx = t & 15;
    const int ty = t >> 4;
    const int pn = tx * 8;
    const int om = ty * 8;

    // cp.async chunk mapping
    const int b_r0 = t >> 5, b_c0 = (t & 31) * 4;     // rows +0,+6,+12
    const int a_r0 = t / 24, a_c0 = (t % 24) * 4;     // rows +0,+8

    auto issue = [&](int it, int s) {
        const int kb = it * BK;
        cp16(&b_s[s][b_r0][b_c0],      inb + (size_t)(kb + b_r0)      * HW + b_c0);
        cp16(&b_s[s][b_r0 + 6][b_c0],  inb + (size_t)(kb + b_r0 + 6)  * HW + b_c0);
        if (t < 128)
            cp16(&b_s[s][b_r0 + 12][b_c0], inb + (size_t)(kb + b_r0 + 12) * HW + b_c0);
        cp16(&a_s[s][a_r0][a_c0],      wtb + (size_t)(kb + a_r0)      * MT + a_c0);
        cp16(&a_s[s][a_r0 + 8][a_c0],  wtb + (size_t)(kb + a_r0 + 8)  * MT + a_c0);
        asm volatile("cp.async.commit_group;");
    };

    issue(0, 0);
    issue(1, 1);

    ull acc[8][4];
#pragma unroll
    for (int i = 0; i < 8; ++i)
#pragma unroll
        for (int p = 0; p < 4; ++p) acc[i][p] = 0ULL;

    for (int it = 0; it < KITERS; ++it) {
        if (it < KITERS - 1) asm volatile("cp.async.wait_group 1;");
        else                 asm volatile("cp.async.wait_group 0;");
        __syncthreads();
        if (it + 2 < KITERS) issue(it + 2, (it + 2) % 3);

        const int s = it % 3;
#pragma unroll
        for (int kk = 0; kk < BK; ++kk) {
            const float4 wa = *(const float4*)&a_s[s][kk][om];
            const float4 wc = *(const float4*)&a_s[s][kk][om + 4];
            const float4 xa = *(const float4*)&b_s[s][kk][pn];
            const float4 xb = *(const float4*)&b_s[s][kk][pn + 4];
            ull xp[4];
            xp[0] = pack2(xa.x, xa.y); xp[1] = pack2(xa.z, xa.w);
            xp[2] = pack2(xb.x, xb.y); xp[3] = pack2(xb.z, xb.w);
            const float av[8] = {wa.x, wa.y, wa.z, wa.w, wc.x, wc.y, wc.z, wc.w};
#pragma unroll
            for (int i = 0; i < 8; ++i) {
                const ull wp = pack2(av[i], av[i]);
#pragma unroll
                for (int p = 0; p < 4; ++p) acc[i][p] = fma2(wp, xp[p], acc[i][p]);
            }
        }
    }

#pragma unroll
    for (int i = 0; i < 8; ++i) {
        const int o = om + i;
        const float bb = bias[m0 + o];
        float r0, r1, r2, r3;
        unpack2(acc[i][0], r0, r1); unpack2(acc[i][1], r2, r3);
        *(float4*)(outb + (size_t)o * HW + pn) =
            make_float4(r0 + bb, r1 + bb, r2 + bb, r3 + bb);
        unpack2(acc[i][2], r0, r1); unpack2(acc[i][3], r2, r3);
        *(float4*)(outb + (size_t)o * HW + pn + 4) =
            make_float4(r0 + bb, r1 + bb, r2 + bb, r3 + bb);
    }
}

// ---------------------------------------------------------------------------
// C: attention per (window, head) — round-7 proven version.
// Only change: float2 loads for the k pair (phase 3) and v pair (phase 5).
// grid (NW, HEADS), 192 thr, ~30 KB smem.
// ---------------------------------------------------------------------------
__global__ __launch_bounds__(192)
void attn_kernel(const float* __restrict__ w_dw,
                 const float* __restrict__ b_dw,
                 const float* __restrict__ temperature)
{
    __shared__ float q_s[HC * CSTR];
    __shared__ float k_s[HC * CSTR];
    __shared__ float v_s[HC * CSTR];
    __shared__ float at [NPIX * CSTR];
    __shared__ float invq[NPIX], invk[NPIX];

    const int win = blockIdx.x;
    const int h   = blockIdx.y;
    const int t   = threadIdx.x;
    const int b  = win >> 10;
    const int wh = (win >> 5) & 31;
    const int ww = win & 31;

    // ---- phase 0: coalesced load (consecutive threads = consecutive pixels)
    {
        const size_t gbase = (size_t)b * OQ * HW + (size_t)(wh * 7) * IMG + ww * 7;
#pragma unroll
        for (int it = 0; it < 25; ++it) {
            const int u = t + it * 192;
            if (u < 96 * NPIX) {
                const int c = u / NPIX, p = u % NPIX;
                const int sel = c >> 5, cc = c & 31;
                const int ch = sel * CH + h * HC + cc;
                const float v = __ldg(&g_qkv[gbase + (size_t)ch * HW + (p / 7) * IMG + p % 7]);
                float* dstp = (sel == 0) ? q_s : (sel == 1) ? k_s : v_s;
                dstp[cc * CSTR + p] = v;
            }
        }
    }
    __syncthreads();

    // ---- phase 1: dwconv 3x3 in place (window zero-padded) ----
    {
        const int c    = t >> 1;          // 0..95
        const int half = t & 1;
        const int sel  = c >> 5;          // 0=q 1=k 2=v
        const int cc   = c & 31;
        const int ch   = sel * CH + h * HC + cc;
        float* dstp = (sel == 0) ? q_s : (sel == 1) ? k_s : v_s;
        float* row0 = dstp + cc * CSTR;

        float w9[9];
#pragma unroll
        for (int k = 0; k < 9; ++k) w9[k] = w_dw[ch * 9 + k];
        const float bb = b_dw[ch];

        float in[5][7];
        const int r0 = half ? 3 : 0;
        const int nr = half ? 4 : 5;
        for (int r = 0; r < nr; ++r)
#pragma unroll
            for (int j = 0; j < 7; ++j) in[r][j] = row0[(r0 + r) * 7 + j];
        __syncthreads();   // all reads done before in-place writes

        if (!half) {
#pragma unroll
            for (int i = 0; i < 4; ++i) {
#pragma unroll
                for (int j = 0; j < 7; ++j) {
                    float s = bb;
#pragma unroll
                    for (int di = -1; di <= 1; ++di) {
                        const int ii = i + di;
                        if (ii < 0) continue;
#pragma unroll
                        for (int dj = -1; dj <= 1; ++dj) {
                            const int jj = j + dj;
                            if (jj >= 0 && jj < 7)
                                s += w9[(di + 1) * 3 + (dj + 1)] * in[ii][jj];
                        }
                    }
                    row0[i * 7 + j] = s;
                }
            }
        } else {
#pragma unroll
            for (int i = 4; i < 7; ++i) {
#pragma unroll
                for (int j = 0; j < 7; ++j) {
                    float s = bb;
#pragma unroll
                    for (int di = -1; di <= 1; ++di) {
                        const int ii = i + di;
                        if (ii > 6) continue;
#pragma unroll
                        for (int dj = -1; dj <= 1; ++dj) {
                            const int jj = j + dj;
                            if (jj >= 0 && jj < 7)
                                s += w9[(di + 1) * 3 + (dj + 1)] * in[ii - 3][jj];
                        }
                    }
                    row0[i * 7 + j] = s;
                }
            }
        }
    }
    __syncthreads();

    // ---- phase 2: inverse norms (temperature folded into q side) ----
    if (t < 2 * NPIX) {
        const int part = t / NPIX, p = t % NPIX;
        const float* s = part ? k_s : q_s;
        float acc = 0.f;
#pragma unroll
        for (int c = 0; c < HC; ++c) { const float v = s[c * CSTR + p]; acc += v * v; }
        const float nm = fmaxf(sqrtf(acc), 1e-12f);
        if (part == 0) invq[p] = temperature[h] / nm;
        else           invk[p] = 1.f / nm;
    }
    __syncthreads();

    // ---- phase 3: attn[n][m] = (sum_c k[c][n]*q[c][m]) * invk[n]*invq[m] ----
    if (t < 175) {
        const int n0 = 2 * (t / 7), m0 = 7 * (t % 7);
        const bool hasN1 = (n0 + 1 < NPIX);
        float a0[7], a1[7];
#pragma unroll
        for (int jm = 0; jm < 7; ++jm) { a0[jm] = 0.f; a1[jm] = 0.f; }
#pragma unroll
        for (int c = 0; c < HC; ++c) {
            // n0 is even -> 8B-aligned pair load (n0=48 reads pad slot 49; a1 discarded)
            const float2 kk2 = *(const float2*)&k_s[c * CSTR + n0];
            const float k0 = kk2.x;
            const float k1 = kk2.y;
#pragma unroll
            for (int jm = 0; jm < 7; ++jm) {
                const float qv = q_s[c * CSTR + m0 + jm];
                a0[jm] += k0 * qv;
                a1[jm] += k1 * qv;
            }
        }
        const float ik0 = invk[n0];
#pragma unroll
        for (int jm = 0; jm < 7; ++jm)
            at[n0 * CSTR + m0 + jm] = a0[jm] * ik0 * invq[m0 + jm];
        if (hasN1) {
            const float ik1 = invk[n0 + 1];
#pragma unroll
            for (int jm = 0; jm < 7; ++jm)
                at[(n0 + 1) * CSTR + m0 + jm] = a1[jm] * ik1 * invq[m0 + jm];
        }
    }
    __syncthreads();

    // ---- phase 4: softmax over n per column m (2 threads/col + shfl) ----
    {
        const int m = (t < 98) ? (t >> 1) : 0;   // dummies track col 0
        const int part = t & 1;
        float mx = -1e30f;
        for (int n = part; n < NPIX; n += 2) mx = fmaxf(mx, at[n * CSTR + m]);
        mx = fmaxf(mx, __shfl_xor_sync(0xffffffffu, mx, 1));
        float ev[25];
        float ssum = 0.f;
        int cnt = 0;
        for (int n = part; n < NPIX; n += 2) {
            const float e = __expf(at[n * CSTR + m] - mx);
            ev[cnt++] = e;
            ssum += e;
        }
        ssum += __shfl_xor_sync(0xffffffffu, ssum, 1);
        const float r = 1.f / ssum;
        __syncthreads();   // all reads of at done before stores
        if (t < 98) {
            cnt = 0;
            for (int n = part; n < NPIX; n += 2) at[n * CSTR + m] = ev[cnt++] * r;
        }
    }
    __syncthreads();

    // ---- phase 5: out[c][m] = sum_n v[c][n]*attn[n][m], all 192 threads ----
    for (int u = t; u < HC * 7; u += 192) {      // 224 units: (channel, row-group)
        const int c = u / 7, mg = u % 7;
        const int m0 = 7 * mg;
        float a[7];
#pragma unroll
        for (int jm = 0; jm < 7; ++jm) a[jm] = 0.f;
#pragma unroll 4
        for (int n = 0; n < 48; n += 2) {
            const float2 vv = *(const float2*)&v_s[c * CSTR + n];   // 8B aligned
#pragma unroll
            for (int jm = 0; jm < 7; ++jm) {
                a[jm] += vv.x * at[n * CSTR + m0 + jm];
                a[jm] += vv.y * at[(n + 1) * CSTR + m0 + jm];
            }
        }
        const float v48 = v_s[c * CSTR + 48];
#pragma unroll
        for (int jm = 0; jm < 7; ++jm) a[jm] += v48 * at[48 * CSTR + m0 + jm];

        float* dst = g_attn + (((size_t)(b * CH + h * HC + c) * IMG) + wh * 7 + mg) * IMG + ww * 7;
#pragma unroll
        for (int jm = 0; jm < 7; ++jm) dst[jm] = a[jm];
    }
}

// ---------------------------------------------------------------------------
extern "C" void kernel_launch(void* const* d_in, const int* in_sizes, int n_in,
                              void* d_out, int out_size)
{
    const float* x      = (const float*)d_in[0];
    const float* w_qkv  = (const float*)d_in[1];
    const float* b_qkv  = (const float*)d_in[2];
    const float* w_dw   = (const float*)d_in[3];
    const float* b_dw   = (const float*)d_in[4];
    const float* w_proj = (const float*)d_in[5];
    const float* b_proj = (const float*)d_in[6];
    const float* temp   = (const float*)d_in[7];
    float* out = (float*)d_out;

    // T: transpose weights into K-major scratch
    transpose_w<<<(OQ * CH + 255) / 256, 256>>>(w_qkv, OQ, 0);
    transpose_w<<<(CH * CH + 255) / 256, 256>>>(w_proj, CH, OQ * CH);
    // A: QKV GEMM -> g_qkv
    conv1x1_kernel<OQ, 0><<<dim3(HW / BN, OQ / BM, BATCH), 192>>>(x, b_qkv, nullptr);
    // C: fused dwconv + attention -> g_attn
    attn_kernel<<<dim3(NW, HEADS), 192>>>(w_dw, b_dw, temp);
    // D: proj GEMM -> out
    conv1x1_kernel<CH, 1><<<dim3(HW / BN, CH / BM, BATCH), 192>>>(nullptr, b_proj, out);
}

// round 9
// speedup vs baseline: 1.1353x; 1.0319x over previous
#include <cuda_runtime.h>
#include <cstdint>

// ---------------------------------------------------------------------------
// Windowed XCA attention, fp32. B=4, C=192, H=W=224, WS=7 -> nW=4096 windows.
//   T: transpose w_qkv / w_proj into K-major scratch (tiny)
//   A: QKV dense GEMM  (cp.async 3-stage, 8x8 tile, 3 CTA/SM) -> g_qkv
//   C: per (window,head): dwconv3x3 + norms + KtQ(4n-tile) + softmax
//      + V*attn(2c-tile)                                      -> g_attn
//   D: proj dense GEMM  (same template)                       -> out
// ---------------------------------------------------------------------------

#define BATCH 4
#define CH    192
#define IMG   224
#define HW    50176
#define HEADS 6
#define HC    32
#define NW    4096
#define OQ    576
#define NPIX  49
#define CSTR  50

typedef unsigned long long ull;

__device__ float g_qkv [(size_t)BATCH * OQ * HW];    // 462 MB
__device__ float g_attn[(size_t)BATCH * CH * HW];    // 154 MB
__device__ float g_wt[(OQ + CH) * CH];               // transposed weights

__device__ __forceinline__ ull pack2(float lo, float hi) {
    ull r; asm("mov.b64 %0, {%1, %2};" : "=l"(r) : "f"(lo), "f"(hi)); return r;
}
__device__ __forceinline__ void unpack2(ull v, float& lo, float& hi) {
    asm("mov.b64 {%0, %1}, %2;" : "=f"(lo), "=f"(hi) : "l"(v));
}
__device__ __forceinline__ ull fma2(ull a, ull b, ull c) {
    ull d; asm("fma.rn.f32x2 %0, %1, %2, %3;" : "=l"(d) : "l"(a), "l"(b), "l"(c)); return d;
}
__device__ __forceinline__ void cp16(void* dst, const void* src) {
    unsigned d = (unsigned)__cvta_generic_to_shared(dst);
    asm volatile("cp.async.cg.shared.global [%0], [%1], 16;" :: "r"(d), "l"(src));
}

// ---------------------------------------------------------------------------
// T: transpose weights: g_wt[off + c*M + o] = src[o*CH + c]
// ---------------------------------------------------------------------------
__global__ void transpose_w(const float* __restrict__ src, int M, int off)
{
    const int i = blockIdx.x * 256 + threadIdx.x;
    if (i < M * CH) {
        const int o = i / CH, c = i % CH;
        g_wt[off + c * M + o] = src[i];
    }
}

// ---------------------------------------------------------------------------
// A/D: 1x1 conv dense GEMM, cp.async 3-stage pipeline (round-6 proven).
// Block tile 96(M) x 128(N), BK=16, 192 threads, thread tile 8x8 (f32x2).
// ---------------------------------------------------------------------------
#define BM 96
#define BN 128
#define BK 16
#define KITERS (CH / BK)   // 12

template<int MT, int MODE>
__global__ __launch_bounds__(192, 3)
void conv1x1_kernel(const float* __restrict__ in_p,
                    const float* __restrict__ bias,
                    float* __restrict__ out_p)
{
    __shared__ __align__(16) float a_s[3][BK][100];   // K-major weight tile
    __shared__ __align__(16) float b_s[3][BK][BN];    // input pixel tile

    const float* in = (MODE == 0) ? in_p : (const float*)g_attn;
    float* out      = (MODE == 0) ? (float*)g_qkv : out_p;
    const float* wt = g_wt + (MODE == 0 ? 0 : OQ * CH);

    const int t  = threadIdx.x;
    const int n0 = blockIdx.x * BN;
    const int m0 = blockIdx.y * BM;
    const int b  = blockIdx.z;

    const float* inb = in + (size_t)b * CH * HW + n0;
    const float* wtb = wt + m0;                   // row stride MT
    float* outb = out + ((size_t)b * MT + m0) * HW + n0;

    const int tx = t & 15;
    const int ty = t >> 4;
    const int pn = tx * 8;
    const int om = ty * 8;

    // cp.async chunk mapping
    const int b_r0 = t >> 5, b_c0 = (t & 31) * 4;     // rows +0,+6,+12
    const int a_r0 = t / 24, a_c0 = (t % 24) * 4;     // rows +0,+8

    auto issue = [&](int it, int s) {
        const int kb = it * BK;
        cp16(&b_s[s][b_r0][b_c0],      inb + (size_t)(kb + b_r0)      * HW + b_c0);
        cp16(&b_s[s][b_r0 + 6][b_c0],  inb + (size_t)(kb + b_r0 + 6)  * HW + b_c0);
        if (t < 128)
            cp16(&b_s[s][b_r0 + 12][b_c0], inb + (size_t)(kb + b_r0 + 12) * HW + b_c0);
        cp16(&a_s[s][a_r0][a_c0],      wtb + (size_t)(kb + a_r0)      * MT + a_c0);
        cp16(&a_s[s][a_r0 + 8][a_c0],  wtb + (size_t)(kb + a_r0 + 8)  * MT + a_c0);
        asm volatile("cp.async.commit_group;");
    };

    issue(0, 0);
    issue(1, 1);

    ull acc[8][4];
#pragma unroll
    for (int i = 0; i < 8; ++i)
#pragma unroll
        for (int p = 0; p < 4; ++p) acc[i][p] = 0ULL;

    for (int it = 0; it < KITERS; ++it) {
        if (it < KITERS - 1) asm volatile("cp.async.wait_group 1;");
        else                 asm volatile("cp.async.wait_group 0;");
        __syncthreads();
        if (it + 2 < KITERS) issue(it + 2, (it + 2) % 3);

        const int s = it % 3;
#pragma unroll
        for (int kk = 0; kk < BK; ++kk) {
            const float4 wa = *(const float4*)&a_s[s][kk][om];
            const float4 wc = *(const float4*)&a_s[s][kk][om + 4];
            const float4 xa = *(const float4*)&b_s[s][kk][pn];
            const float4 xb = *(const float4*)&b_s[s][kk][pn + 4];
            ull xp[4];
            xp[0] = pack2(xa.x, xa.y); xp[1] = pack2(xa.z, xa.w);
            xp[2] = pack2(xb.x, xb.y); xp[3] = pack2(xb.z, xb.w);
            const float av[8] = {wa.x, wa.y, wa.z, wa.w, wc.x, wc.y, wc.z, wc.w};
#pragma unroll
            for (int i = 0; i < 8; ++i) {
                const ull wp = pack2(av[i], av[i]);
#pragma unroll
                for (int p = 0; p < 4; ++p) acc[i][p] = fma2(wp, xp[p], acc[i][p]);
            }
        }
    }

#pragma unroll
    for (int i = 0; i < 8; ++i) {
        const int o = om + i;
        const float bb = bias[m0 + o];
        float r0, r1, r2, r3;
        unpack2(acc[i][0], r0, r1); unpack2(acc[i][1], r2, r3);
        *(float4*)(outb + (size_t)o * HW + pn) =
            make_float4(r0 + bb, r1 + bb, r2 + bb, r3 + bb);
        unpack2(acc[i][2], r0, r1); unpack2(acc[i][3], r2, r3);
        *(float4*)(outb + (size_t)o * HW + pn + 4) =
            make_float4(r0 + bb, r1 + bb, r2 + bb, r3 + bb);
    }
}

// ---------------------------------------------------------------------------
// C: attention per (window, head). grid (NW, HEADS), 192 thr, ~30 KB smem.
// Phase 3: 4n x 7m register tile. Phase 5: 2c x 7m register tile.
// ---------------------------------------------------------------------------
__global__ __launch_bounds__(192)
void attn_kernel(const float* __restrict__ w_dw,
                 const float* __restrict__ b_dw,
                 const float* __restrict__ temperature)
{
    __shared__ float q_s[HC * CSTR];
    __shared__ float k_s[HC * CSTR + 4];   // +4 pad: n0=48 vector load stays in-bounds
    __shared__ float v_s[HC * CSTR];
    __shared__ float at [NPIX * CSTR];
    __shared__ float invq[NPIX], invk[NPIX];

    const int win = blockIdx.x;
    const int h   = blockIdx.y;
    const int t   = threadIdx.x;
    const int b  = win >> 10;
    const int wh = (win >> 5) & 31;
    const int ww = win & 31;

    // ---- phase 0: coalesced load (consecutive threads = consecutive pixels)
    {
        const size_t gbase = (size_t)b * OQ * HW + (size_t)(wh * 7) * IMG + ww * 7;
#pragma unroll
        for (int it = 0; it < 25; ++it) {
            const int u = t + it * 192;
            if (u < 96 * NPIX) {
                const int c = u / NPIX, p = u % NPIX;
                const int sel = c >> 5, cc = c & 31;
                const int ch = sel * CH + h * HC + cc;
                const float v = __ldg(&g_qkv[gbase + (size_t)ch * HW + (p / 7) * IMG + p % 7]);
                float* dstp = (sel == 0) ? q_s : (sel == 1) ? k_s : v_s;
                dstp[cc * CSTR + p] = v;
            }
        }
    }
    __syncthreads();

    // ---- phase 1: dwconv 3x3 in place (window zero-padded) ----
    {
        const int c    = t >> 1;          // 0..95
        const int half = t & 1;
        const int sel  = c >> 5;          // 0=q 1=k 2=v
        const int cc   = c & 31;
        const int ch   = sel * CH + h * HC + cc;
        float* dstp = (sel == 0) ? q_s : (sel == 1) ? k_s : v_s;
        float* row0 = dstp + cc * CSTR;

        float w9[9];
#pragma unroll
        for (int k = 0; k < 9; ++k) w9[k] = w_dw[ch * 9 + k];
        const float bb = b_dw[ch];

        float in[5][7];
        const int r0 = half ? 3 : 0;
        const int nr = half ? 4 : 5;
        for (int r = 0; r < nr; ++r)
#pragma unroll
            for (int j = 0; j < 7; ++j) in[r][j] = row0[(r0 + r) * 7 + j];
        __syncthreads();   // all reads done before in-place writes

        if (!half) {
#pragma unroll
            for (int i = 0; i < 4; ++i) {
#pragma unroll
                for (int j = 0; j < 7; ++j) {
                    float s = bb;
#pragma unroll
                    for (int di = -1; di <= 1; ++di) {
                        const int ii = i + di;
                        if (ii < 0) continue;
#pragma unroll
                        for (int dj = -1; dj <= 1; ++dj) {
                            const int jj = j + dj;
                            if (jj >= 0 && jj < 7)
                                s += w9[(di + 1) * 3 + (dj + 1)] * in[ii][jj];
                        }
                    }
                    row0[i * 7 + j] = s;
                }
            }
        } else {
#pragma unroll
            for (int i = 4; i < 7; ++i) {
#pragma unroll
                for (int j = 0; j < 7; ++j) {
                    float s = bb;
#pragma unroll
                    for (int di = -1; di <= 1; ++di) {
                        const int ii = i + di;
                        if (ii > 6) continue;
#pragma unroll
                        for (int dj = -1; dj <= 1; ++dj) {
                            const int jj = j + dj;
                            if (jj >= 0 && jj < 7)
                                s += w9[(di + 1) * 3 + (dj + 1)] * in[ii - 3][jj];
                        }
                    }
                    row0[i * 7 + j] = s;
                }
            }
        }
    }
    __syncthreads();

    // ---- phase 2: inverse norms (temperature folded into q side) ----
    if (t < 2 * NPIX) {
        const int part = t / NPIX, p = t % NPIX;
        const float* s = part ? k_s : q_s;
        float acc = 0.f;
#pragma unroll
        for (int c = 0; c < HC; ++c) { const float v = s[c * CSTR + p]; acc += v * v; }
        const float nm = fmaxf(sqrtf(acc), 1e-12f);
        if (part == 0) invq[p] = temperature[h] / nm;
        else           invk[p] = 1.f / nm;
    }
    __syncthreads();

    // ---- phase 3: attn[n][m] = (sum_c k[c][n]*q[c][m]) * invk[n]*invq[m]
    //      4n x 7m register tile: 13 n-groups x 7 m-groups = 91 threads ----
    if (t < 91) {
        const int n0 = 4 * (t / 7);        // 0,4,...,48
        const int m0 = 7 * (t % 7);
        float a0[7], a1[7], a2[7], a3[7];
#pragma unroll
        for (int jm = 0; jm < 7; ++jm) { a0[jm] = a1[jm] = a2[jm] = a3[jm] = 0.f; }
#pragma unroll
        for (int c = 0; c < HC; ++c) {
            const float2 ka = *(const float2*)&k_s[c * CSTR + n0];       // 8B aligned
            const float2 kb = *(const float2*)&k_s[c * CSTR + n0 + 2];   // pad-covered
#pragma unroll
            for (int jm = 0; jm < 7; ++jm) {
                const float qv = q_s[c * CSTR + m0 + jm];
                a0[jm] += ka.x * qv;
                a1[jm] += ka.y * qv;
                a2[jm] += kb.x * qv;
                a3[jm] += kb.y * qv;
            }
        }
        const float ik0 = invk[n0];
#pragma unroll
        for (int jm = 0; jm < 7; ++jm)
            at[n0 * CSTR + m0 + jm] = a0[jm] * ik0 * invq[m0 + jm];
        if (n0 + 1 < NPIX) {
            const float ik1 = invk[n0 + 1];
            const float ik2 = invk[n0 + 2];
            const float ik3 = invk[n0 + 3];
#pragma unroll
            for (int jm = 0; jm < 7; ++jm) {
                const float iq = invq[m0 + jm];
                at[(n0 + 1) * CSTR + m0 + jm] = a1[jm] * ik1 * iq;
                at[(n0 + 2) * CSTR + m0 + jm] = a2[jm] * ik2 * iq;
                at[(n0 + 3) * CSTR + m0 + jm] = a3[jm] * ik3 * iq;
            }
        }
    }
    __syncthreads();

    // ---- phase 4: softmax over n per column m (2 threads/col + shfl) ----
    {
        const int m = (t < 98) ? (t >> 1) : 0;   // dummies track col 0
        const int part = t & 1;
        float mx = -1e30f;
        for (int n = part; n < NPIX; n += 2) mx = fmaxf(mx, at[n * CSTR + m]);
        mx = fmaxf(mx, __shfl_xor_sync(0xffffffffu, mx, 1));
        float ev[25];
        float ssum = 0.f;
        int cnt = 0;
        for (int n = part; n < NPIX; n += 2) {
            const float e = __expf(at[n * CSTR + m] - mx);
            ev[cnt++] = e;
            ssum += e;
        }
        ssum += __shfl_xor_sync(0xffffffffu, ssum, 1);
        const float r = 1.f / ssum;
        __syncthreads();   // all reads of at done before stores
        if (t < 98) {
            cnt = 0;
            for (int n = part; n < NPIX; n += 2) at[n * CSTR + m] = ev[cnt++] * r;
        }
    }
    __syncthreads();

    // ---- phase 5: out[c][m] = sum_n v[c][n]*attn[n][m]
    //      2c x 7m register tile: 16 c-pairs x 7 m-groups = 112 threads ----
    if (t < 112) {
        const int c0 = 2 * (t / 7), mg = t % 7;
        const int m0 = 7 * mg;
        float a0[7], a1[7];
#pragma unroll
        for (int jm = 0; jm < 7; ++jm) { a0[jm] = 0.f; a1[jm] = 0.f; }
#pragma unroll 4
        for (int n = 0; n < 48; n += 2) {
            const float2 v0 = *(const float2*)&v_s[c0 * CSTR + n];        // 8B aligned
            const float2 v1 = *(const float2*)&v_s[(c0 + 1) * CSTR + n];
#pragma unroll
            for (int jm = 0; jm < 7; ++jm) {
                const float at0 = at[n * CSTR + m0 + jm];
                const float at1 = at[(n + 1) * CSTR + m0 + jm];
                a0[jm] += v0.x * at0 + v0.y * at1;
                a1[jm] += v1.x * at0 + v1.y * at1;
            }
        }
        const float v48_0 = v_s[c0 * CSTR + 48];
        const float v48_1 = v_s[(c0 + 1) * CSTR + 48];
#pragma unroll
        for (int jm = 0; jm < 7; ++jm) {
            const float at48 = at[48 * CSTR + m0 + jm];
            a0[jm] += v48_0 * at48;
            a1[jm] += v48_1 * at48;
        }

        float* dst = g_attn + (((size_t)(b * CH + h * HC + c0) * IMG) + wh * 7 + mg) * IMG + ww * 7;
#pragma unroll
        for (int jm = 0; jm < 7; ++jm) dst[jm] = a0[jm];
        dst += (size_t)IMG * IMG;
#pragma unroll
        for (int jm = 0; jm < 7; ++jm) dst[jm] = a1[jm];
    }
}

// ---------------------------------------------------------------------------
extern "C" void kernel_launch(void* const* d_in, const int* in_sizes, int n_in,
                              void* d_out, int out_size)
{
    const float* x      = (const float*)d_in[0];
    const float* w_qkv  = (const float*)d_in[1];
    const float* b_qkv  = (const float*)d_in[2];
    const float* w_dw   = (const float*)d_in[3];
    const float* b_dw   = (const float*)d_in[4];
    const float* w_proj = (const float*)d_in[5];
    const float* b_proj = (const float*)d_in[6];
    const float* temp   = (const float*)d_in[7];
    float* out = (float*)d_out;

    // T: transpose weights into K-major scratch
    transpose_w<<<(OQ * CH + 255) / 256, 256>>>(w_qkv, OQ, 0);
    transpose_w<<<(CH * CH + 255) / 256, 256>>>(w_proj, CH, OQ * CH);
    // A: QKV GEMM -> g_qkv
    conv1x1_kernel<OQ, 0><<<dim3(HW / BN, OQ / BM, BATCH), 192>>>(x, b_qkv, nullptr);
    // C: fused dwconv + attention -> g_attn
    attn_kernel<<<dim3(NW, HEADS), 192>>>(w_dw, b_dw, temp);
    // D: proj GEMM -> out
    conv1x1_kernel<CH, 1><<<dim3(HW / BN, CH / BM, BATCH), 192>>>(nullptr, b_proj, out);
}

// round 10
// speedup vs baseline: 1.1379x; 1.0022x over previous
#include <cuda_runtime.h>
#include <cstdint>

// ---------------------------------------------------------------------------
// Windowed XCA attention, fp32. B=4, C=192, H=W=224, WS=7 -> nW=4096 windows.
//   T: transpose w_qkv / w_proj into K-major scratch (tiny)
//   A: QKV dense GEMM  (cp.async 3-stage, 16x8 thread tile) -> g_qkv
//   C: per (window,head): dwconv3x3 + norms + KtQ(4n) + softmax + V*attn(2c)
//   D: proj dense GEMM  (same template)                     -> out
// ---------------------------------------------------------------------------

#define BATCH 4
#define CH    192
#define IMG   224
#define HW    50176
#define HEADS 6
#define HC    32
#define NW    4096
#define OQ    576
#define NPIX  49
#define CSTR  50

typedef unsigned long long ull;

__device__ float g_qkv [(size_t)BATCH * OQ * HW];    // 462 MB
__device__ float g_attn[(size_t)BATCH * CH * HW];    // 154 MB
__device__ float g_wt[(OQ + CH) * CH];               // transposed weights

__device__ __forceinline__ ull pack2(float lo, float hi) {
    ull r; asm("mov.b64 %0, {%1, %2};" : "=l"(r) : "f"(lo), "f"(hi)); return r;
}
__device__ __forceinline__ void unpack2(ull v, float& lo, float& hi) {
    asm("mov.b64 {%0, %1}, %2;" : "=f"(lo), "=f"(hi) : "l"(v));
}
__device__ __forceinline__ ull fma2(ull a, ull b, ull c) {
    ull d; asm("fma.rn.f32x2 %0, %1, %2, %3;" : "=l"(d) : "l"(a), "l"(b), "l"(c)); return d;
}
__device__ __forceinline__ void cp16(void* dst, const void* src) {
    unsigned d = (unsigned)__cvta_generic_to_shared(dst);
    asm volatile("cp.async.cg.shared.global [%0], [%1], 16;" :: "r"(d), "l"(src));
}

// ---------------------------------------------------------------------------
// T: transpose weights: g_wt[off + c*M + o] = src[o*CH + c]
// ---------------------------------------------------------------------------
__global__ void transpose_w(const float* __restrict__ src, int M, int off)
{
    const int i = blockIdx.x * 256 + threadIdx.x;
    if (i < M * CH) {
        const int o = i / CH, c = i % CH;
        g_wt[off + c * M + o] = src[i];
    }
}

// ---------------------------------------------------------------------------
// A/D: 1x1 conv dense GEMM, cp.async 3-stage, thread tile 16(M) x 8(N).
// Block tile 192(M) x 128(N), BK=16, 192 threads (12 ty x 16 tx).
// Dynamic smem: a_s[3][16][200] + b_s[3][16][128] = 62976 B.
// ---------------------------------------------------------------------------
#define BM 192
#define BN 128
#define BK 16
#define KITERS (CH / BK)   // 12
#define ASTR 200                       // a row stride (floats)
#define A_STAGE (BK * ASTR)            // 3200
#define B_STAGE (BK * BN)              // 2048
#define GEMM_SMEM ((3 * A_STAGE + 3 * B_STAGE) * 4)

template<int MT, int MODE>
__global__ __launch_bounds__(192, 2)
void conv1x1_kernel(const float* __restrict__ in_p,
                    const float* __restrict__ bias,
                    float* __restrict__ out_p)
{
    extern __shared__ float sm[];
    float* a_base = sm;                    // [3][16][200]
    float* b_base = sm + 3 * A_STAGE;      // [3][16][128]

    const float* in = (MODE == 0) ? in_p : (const float*)g_attn;
    float* out      = (MODE == 0) ? (float*)g_qkv : out_p;
    const float* wt = g_wt + (MODE == 0 ? 0 : OQ * CH);

    const int t  = threadIdx.x;
    const int n0 = blockIdx.x * BN;
    const int m0 = blockIdx.y * BM;
    const int b  = blockIdx.z;

    const float* inb = in + (size_t)b * CH * HW + n0;
    const float* wtb = wt + m0;                   // row stride MT
    float* outb = out + ((size_t)b * MT + m0) * HW + n0;

    const int tx = t & 15;
    const int ty = t >> 4;
    const int pn = tx * 8;
    const int om = ty * 16;

    // cp.async chunk mapping
    const int b_r0 = t >> 5, b_c0 = (t & 31) * 4;     // rows +0,+6,+12 (t<128 for +12)
    int a_r[4], a_c[4];                               // 768 f4 = 4 * 192
#pragma unroll
    for (int i = 0; i < 4; ++i) {
        const int u = t + i * 192;
        a_r[i] = u / 48;
        a_c[i] = (u % 48) * 4;
    }

    auto issue = [&](int it, int s) {
        const int kb = it * BK;
        float* bs = b_base + s * B_STAGE;
        float* as = a_base + s * A_STAGE;
        cp16(bs + b_r0 * BN + b_c0,        inb + (size_t)(kb + b_r0)      * HW + b_c0);
        cp16(bs + (b_r0 + 6) * BN + b_c0,  inb + (size_t)(kb + b_r0 + 6)  * HW + b_c0);
        if (t < 128)
            cp16(bs + (b_r0 + 12) * BN + b_c0, inb + (size_t)(kb + b_r0 + 12) * HW + b_c0);
#pragma unroll
        for (int i = 0; i < 4; ++i)
            cp16(as + a_r[i] * ASTR + a_c[i], wtb + (size_t)(kb + a_r[i]) * MT + a_c[i]);
        asm volatile("cp.async.commit_group;");
    };

    issue(0, 0);
    issue(1, 1);

    ull acc[16][4];
#pragma unroll
    for (int i = 0; i < 16; ++i)
#pragma unroll
        for (int p = 0; p < 4; ++p) acc[i][p] = 0ULL;

    for (int it = 0; it < KITERS; ++it) {
        if (it < KITERS - 1) asm volatile("cp.async.wait_group 1;");
        else                 asm volatile("cp.async.wait_group 0;");
        __syncthreads();
        if (it + 2 < KITERS) issue(it + 2, (it + 2) % 3);

        const int s = it % 3;
        const float* as = a_base + s * A_STAGE;
        const float* bs = b_base + s * B_STAGE;
#pragma unroll
        for (int kk = 0; kk < BK; ++kk) {
            const float4 w0 = *(const float4*)&as[kk * ASTR + om];
            const float4 w1 = *(const float4*)&as[kk * ASTR + om + 4];
            const float4 w2 = *(const float4*)&as[kk * ASTR + om + 8];
            const float4 w3 = *(const float4*)&as[kk * ASTR + om + 12];
            const float4 xa = *(const float4*)&bs[kk * BN + pn];
            const float4 xb = *(const float4*)&bs[kk * BN + pn + 4];
            ull xp[4];
            xp[0] = pack2(xa.x, xa.y); xp[1] = pack2(xa.z, xa.w);
            xp[2] = pack2(xb.x, xb.y); xp[3] = pack2(xb.z, xb.w);
            const float av[16] = {w0.x, w0.y, w0.z, w0.w, w1.x, w1.y, w1.z, w1.w,
                                  w2.x, w2.y, w2.z, w2.w, w3.x, w3.y, w3.z, w3.w};
#pragma unroll
            for (int i = 0; i < 16; ++i) {
                const ull wp = pack2(av[i], av[i]);
#pragma unroll
                for (int p = 0; p < 4; ++p) acc[i][p] = fma2(wp, xp[p], acc[i][p]);
            }
        }
    }

#pragma unroll
    for (int i = 0; i < 16; ++i) {
        const int o = om + i;
        const float bb = bias[m0 + o];
        float r0, r1, r2, r3;
        unpack2(acc[i][0], r0, r1); unpack2(acc[i][1], r2, r3);
        *(float4*)(outb + (size_t)o * HW + pn) =
            make_float4(r0 + bb, r1 + bb, r2 + bb, r3 + bb);
        unpack2(acc[i][2], r0, r1); unpack2(acc[i][3], r2, r3);
        *(float4*)(outb + (size_t)o * HW + pn + 4) =
            make_float4(r0 + bb, r1 + bb, r2 + bb, r3 + bb);
    }
}

// ---------------------------------------------------------------------------
// C: attention per (window, head) — round-9 proven version (frozen).
// grid (NW, HEADS), 192 thr, ~30 KB smem.
// ---------------------------------------------------------------------------
__global__ __launch_bounds__(192)
void attn_kernel(const float* __restrict__ w_dw,
                 const float* __restrict__ b_dw,
                 const float* __restrict__ temperature)
{
    __shared__ float q_s[HC * CSTR];
    __shared__ float k_s[HC * CSTR + 4];   // +4 pad: n0=48 vector load stays in-bounds
    __shared__ float v_s[HC * CSTR];
    __shared__ float at [NPIX * CSTR];
    __shared__ float invq[NPIX], invk[NPIX];

    const int win = blockIdx.x;
    const int h   = blockIdx.y;
    const int t   = threadIdx.x;
    const int b  = win >> 10;
    const int wh = (win >> 5) & 31;
    const int ww = win & 31;

    // ---- phase 0: coalesced load (consecutive threads = consecutive pixels)
    {
        const size_t gbase = (size_t)b * OQ * HW + (size_t)(wh * 7) * IMG + ww * 7;
#pragma unroll
        for (int it = 0; it < 25; ++it) {
            const int u = t + it * 192;
            if (u < 96 * NPIX) {
                const int c = u / NPIX, p = u % NPIX;
                const int sel = c >> 5, cc = c & 31;
                const int ch = sel * CH + h * HC + cc;
                const float v = __ldg(&g_qkv[gbase + (size_t)ch * HW + (p / 7) * IMG + p % 7]);
                float* dstp = (sel == 0) ? q_s : (sel == 1) ? k_s : v_s;
                dstp[cc * CSTR + p] = v;
            }
        }
    }
    __syncthreads();

    // ---- phase 1: dwconv 3x3 in place (window zero-padded) ----
    {
        const int c    = t >> 1;          // 0..95
        const int half = t & 1;
        const int sel  = c >> 5;          // 0=q 1=k 2=v
        const int cc   = c & 31;
        const int ch   = sel * CH + h * HC + cc;
        float* dstp = (sel == 0) ? q_s : (sel == 1) ? k_s : v_s;
        float* row0 = dstp + cc * CSTR;

        float w9[9];
#pragma unroll
        for (int k = 0; k < 9; ++k) w9[k] = w_dw[ch * 9 + k];
        const float bb = b_dw[ch];

        float in[5][7];
        const int r0 = half ? 3 : 0;
        const int nr = half ? 4 : 5;
        for (int r = 0; r < nr; ++r)
#pragma unroll
            for (int j = 0; j < 7; ++j) in[r][j] = row0[(r0 + r) * 7 + j];
        __syncthreads();   // all reads done before in-place writes

        if (!half) {
#pragma unroll
            for (int i = 0; i < 4; ++i) {
#pragma unroll
                for (int j = 0; j < 7; ++j) {
                    float s = bb;
#pragma unroll
                    for (int di = -1; di <= 1; ++di) {
                        const int ii = i + di;
                        if (ii < 0) continue;
#pragma unroll
                        for (int dj = -1; dj <= 1; ++dj) {
                            const int jj = j + dj;
                            if (jj >= 0 && jj < 7)
                                s += w9[(di + 1) * 3 + (dj + 1)] * in[ii][jj];
                        }
                    }
                    row0[i * 7 + j] = s;
                }
            }
        } else {
#pragma unroll
            for (int i = 4; i < 7; ++i) {
#pragma unroll
                for (int j = 0; j < 7; ++j) {
                    float s = bb;
#pragma unroll
                    for (int di = -1; di <= 1; ++di) {
                        const int ii = i + di;
                        if (ii > 6) continue;
#pragma unroll
                        for (int dj = -1; dj <= 1; ++dj) {
                            const int jj = j + dj;
                            if (jj >= 0 && jj < 7)
                                s += w9[(di + 1) * 3 + (dj + 1)] * in[ii - 3][jj];
                        }
                    }
                    row0[i * 7 + j] = s;
                }
            }
        }
    }
    __syncthreads();

    // ---- phase 2: inverse norms (temperature folded into q side) ----
    if (t < 2 * NPIX) {
        const int part = t / NPIX, p = t % NPIX;
        const float* s = part ? k_s : q_s;
        float acc = 0.f;
#pragma unroll
        for (int c = 0; c < HC; ++c) { const float v = s[c * CSTR + p]; acc += v * v; }
        const float nm = fmaxf(sqrtf(acc), 1e-12f);
        if (part == 0) invq[p] = temperature[h] / nm;
        else           invk[p] = 1.f / nm;
    }
    __syncthreads();

    // ---- phase 3: attn[n][m], 4n x 7m register tile (91 threads) ----
    if (t < 91) {
        const int n0 = 4 * (t / 7);        // 0,4,...,48
        const int m0 = 7 * (t % 7);
        float a0[7], a1[7], a2[7], a3[7];
#pragma unroll
        for (int jm = 0; jm < 7; ++jm) { a0[jm] = a1[jm] = a2[jm] = a3[jm] = 0.f; }
#pragma unroll
        for (int c = 0; c < HC; ++c) {
            const float2 ka = *(const float2*)&k_s[c * CSTR + n0];       // 8B aligned
            const float2 kb = *(const float2*)&k_s[c * CSTR + n0 + 2];   // pad-covered
#pragma unroll
            for (int jm = 0; jm < 7; ++jm) {
                const float qv = q_s[c * CSTR + m0 + jm];
                a0[jm] += ka.x * qv;
                a1[jm] += ka.y * qv;
                a2[jm] += kb.x * qv;
                a3[jm] += kb.y * qv;
            }
        }
        const float ik0 = invk[n0];
#pragma unroll
        for (int jm = 0; jm < 7; ++jm)
            at[n0 * CSTR + m0 + jm] = a0[jm] * ik0 * invq[m0 + jm];
        if (n0 + 1 < NPIX) {
            const float ik1 = invk[n0 + 1];
            const float ik2 = invk[n0 + 2];
            const float ik3 = invk[n0 + 3];
#pragma unroll
            for (int jm = 0; jm < 7; ++jm) {
                const float iq = invq[m0 + jm];
                at[(n0 + 1) * CSTR + m0 + jm] = a1[jm] * ik1 * iq;
                at[(n0 + 2) * CSTR + m0 + jm] = a2[jm] * ik2 * iq;
                at[(n0 + 3) * CSTR + m0 + jm] = a3[jm] * ik3 * iq;
            }
        }
    }
    __syncthreads();

    // ---- phase 4: softmax over n per column m (2 threads/col + shfl) ----
    {
        const int m = (t < 98) ? (t >> 1) : 0;   // dummies track col 0
        const int part = t & 1;
        float mx = -1e30f;
        for (int n = part; n < NPIX; n += 2) mx = fmaxf(mx, at[n * CSTR + m]);
        mx = fmaxf(mx, __shfl_xor_sync(0xffffffffu, mx, 1));
        float ev[25];
        float ssum = 0.f;
        int cnt = 0;
        for (int n = part; n < NPIX; n += 2) {
            const float e = __expf(at[n * CSTR + m] - mx);
            ev[cnt++] = e;
            ssum += e;
        }
        ssum += __shfl_xor_sync(0xffffffffu, ssum, 1);
        const float r = 1.f / ssum;
        __syncthreads();   // all reads of at done before stores
        if (t < 98) {
            cnt = 0;
            for (int n = part; n < NPIX; n += 2) at[n * CSTR + m] = ev[cnt++] * r;
        }
    }
    __syncthreads();

    // ---- phase 5: out[c][m], 2c x 7m register tile (112 threads) ----
    if (t < 112) {
        const int c0 = 2 * (t / 7), mg = t % 7;
        const int m0 = 7 * mg;
        float a0[7], a1[7];
#pragma unroll
        for (int jm = 0; jm < 7; ++jm) { a0[jm] = 0.f; a1[jm] = 0.f; }
#pragma unroll 4
        for (int n = 0; n < 48; n += 2) {
            const float2 v0 = *(const float2*)&v_s[c0 * CSTR + n];        // 8B aligned
            const float2 v1 = *(const float2*)&v_s[(c0 + 1) * CSTR + n];
#pragma unroll
            for (int jm = 0; jm < 7; ++jm) {
                const float at0 = at[n * CSTR + m0 + jm];
                const float at1 = at[(n + 1) * CSTR + m0 + jm];
                a0[jm] += v0.x * at0 + v0.y * at1;
                a1[jm] += v1.x * at0 + v1.y * at1;
            }
        }
        const float v48_0 = v_s[c0 * CSTR + 48];
        const float v48_1 = v_s[(c0 + 1) * CSTR + 48];
#pragma unroll
        for (int jm = 0; jm < 7; ++jm) {
            const float at48 = at[48 * CSTR + m0 + jm];
            a0[jm] += v48_0 * at48;
            a1[jm] += v48_1 * at48;
        }

        float* dst = g_attn + (((size_t)(b * CH + h * HC + c0) * IMG) + wh * 7 + mg) * IMG + ww * 7;
#pragma unroll
        for (int jm = 0; jm < 7; ++jm) dst[jm] = a0[jm];
        dst += (size_t)IMG * IMG;
#pragma unroll
        for (int jm = 0; jm < 7; ++jm) dst[jm] = a1[jm];
    }
}

// ---------------------------------------------------------------------------
extern "C" void kernel_launch(void* const* d_in, const int* in_sizes, int n_in,
                              void* d_out, int out_size)
{
    const float* x      = (const float*)d_in[0];
    const float* w_qkv  = (const float*)d_in[1];
    const float* b_qkv  = (const float*)d_in[2];
    const float* w_dw   = (const float*)d_in[3];
    const float* b_dw   = (const float*)d_in[4];
    const float* w_proj = (const float*)d_in[5];
    const float* b_proj = (const float*)d_in[6];
    const float* temp   = (const float*)d_in[7];
    float* out = (float*)d_out;

    cudaFuncSetAttribute(conv1x1_kernel<OQ, 0>,
                         cudaFuncAttributeMaxDynamicSharedMemorySize, GEMM_SMEM);
    cudaFuncSetAttribute(conv1x1_kernel<CH, 1>,
                         cudaFuncAttributeMaxDynamicSharedMemorySize, GEMM_SMEM);

    // T: transpose weights into K-major scratch
    transpose_w<<<(OQ * CH + 255) / 256, 256>>>(w_qkv, OQ, 0);
    transpose_w<<<(CH * CH + 255) / 256, 256>>>(w_proj, CH, OQ * CH);
    // A: QKV GEMM -> g_qkv
    conv1x1_kernel<OQ, 0><<<dim3(HW / BN, OQ / BM, BATCH), 192, GEMM_SMEM>>>(x, b_qkv, nullptr);
    // C: fused dwconv + attention -> g_attn
    attn_kernel<<<dim3(NW, HEADS), 192>>>(w_dw, b_dw, temp);
    // D: proj GEMM -> out
    conv1x1_kernel<CH, 1><<<dim3(HW / BN, CH / BM, BATCH), 192, GEMM_SMEM>>>(nullptr, b_proj, out);
}

// round 12
// speedup vs baseline: 1.2570x; 1.1047x over previous
#include <cuda_runtime.h>
#include <cuda_bf16.h>
#include <mma.h>
#include <cstdint>

using namespace nvcuda;

// ---------------------------------------------------------------------------
// Windowed XCA attention, fp32. B=4, C=192, H=W=224, WS=7 -> nW=4096 windows.
//   W: wprep — weights -> bf16 hi/lo row-major copies
//   X: xprep — activations -> bf16 hi/lo planar copies
//   A: QKV GEMM  WMMA bf16x3 (hi*hi + hi*lo + lo*hi)  -> g_qkv (no bias)
//   C: attention per (window,head), qkv bias folded into load -> g_attn
//   X2: xprep on g_attn;  D: proj GEMM WMMA bf16x3 -> out;  E: +bias
// ---------------------------------------------------------------------------

#define BATCH 4
#define CH    192
#define IMG   224
#define HW    50176
#define HEADS 6
#define HC    32
#define NW    4096
#define OQ    576
#define NPIX  49
#define CSTR  50

#define GBM 96
#define GBN 128
#define GBK 32
#define ASTR 56     // a_s row stride (elements); 112B = 7*16, conflict-free
#define BSTR 136    // b_s row stride (elements); 272B = 17*16, conflict-free

__device__ float g_qkv [(size_t)BATCH * OQ * HW];                 // 462 MB
__device__ float g_attn[(size_t)BATCH * CH * HW];                 // 154 MB
__device__ __nv_bfloat16 g_xb[(size_t)BATCH * 2 * CH * HW];       // 154 MB
__device__ __nv_bfloat16 g_wq[2 * OQ * CH];                       // 442 KB
__device__ __nv_bfloat16 g_wp[2 * CH * CH];                       // 147 KB

__device__ __forceinline__ uint32_t smem_u32(const void* p) {
    uint32_t a;
    asm("{ .reg .u64 t; cvta.to.shared.u64 t, %1; cvt.u32.u64 %0, t; }" : "=r"(a) : "l"(p));
    return a;
}
__device__ __forceinline__ void cp16s(uint32_t d, const void* s) {
    asm volatile("cp.async.cg.shared.global [%0], [%1], 16;" :: "r"(d), "l"(s));
}

// ---------------------------------------------------------------------------
// W: weights -> bf16 hi/lo (row-major, same indexing as source)
// ---------------------------------------------------------------------------
__global__ __launch_bounds__(256) void wprep(const float* __restrict__ wq,
                                             const float* __restrict__ wp)
{
    const int i = blockIdx.x * 256 + threadIdx.x;
    const int NQ = OQ * CH, NP = CH * CH;
    if (i < NQ) {
        const float v = wq[i];
        const __nv_bfloat16 hi = __float2bfloat16(v);
        g_wq[i] = hi;
        g_wq[NQ + i] = __float2bfloat16(v - __bfloat162float(hi));
    } else if (i < NQ + NP) {
        const int j = i - NQ;
        const float v = wp[j];
        const __nv_bfloat16 hi = __float2bfloat16(v);
        g_wp[j] = hi;
        g_wp[NP + j] = __float2bfloat16(v - __bfloat162float(hi));
    }
}

// ---------------------------------------------------------------------------
// X: activations [b][c][p] fp32 -> g_xb[b][split][c][p] bf16 (hi, lo)
// ---------------------------------------------------------------------------
template<int SRC>
__global__ __launch_bounds__(256) void xprep(const float* __restrict__ src_p)
{
    const float* src = (SRC == 0) ? src_p : (const float*)g_attn;
    const size_t q = (size_t)blockIdx.x * 256 + threadIdx.x;   // quad index
    const size_t PER_B = (size_t)CH * HW / 4;                  // quads per batch
    if (q >= (size_t)BATCH * PER_B) return;
    const size_t b = q / PER_B, r = q % PER_B;

    const float4 v = ((const float4*)src)[q];
    __nv_bfloat16 h[4], l[4];
    const float vv[4] = {v.x, v.y, v.z, v.w};
#pragma unroll
    for (int i = 0; i < 4; ++i) {
        h[i] = __float2bfloat16(vv[i]);
        l[i] = __float2bfloat16(vv[i] - __bfloat162float(h[i]));
    }
    const size_t base = (size_t)b * 2 * CH * HW;
    *(unsigned long long*)(g_xb + base + r * 4) = *(const unsigned long long*)h;
    *(unsigned long long*)(g_xb + base + (size_t)CH * HW + r * 4) = *(const unsigned long long*)l;
}

// ---------------------------------------------------------------------------
// GEMM: out[b][o][p] = sum_c w[o][c] * act[b][c][p], WMMA bf16x3.
// CTA 96(M) x 128(N), 192 thr (6 warps, warp tile 32x64), K chunks of 32,
// 18 chunks = 3 split terms x 6, double-buffered cp.async.
// ---------------------------------------------------------------------------
template<int MROWS, int MODE>
__global__ __launch_bounds__(192, 2)
void gemm_wmma(float* __restrict__ out_p)
{
    __shared__ __nv_bfloat16 a_s[2][GBM * ASTR];   // 21504 B
    __shared__ __nv_bfloat16 b_s[2][GBK * BSTR];   // 17408 B

    const int t  = threadIdx.x;
    const int n0 = blockIdx.x * GBN;
    const int m0 = blockIdx.y * GBM;
    const int b  = blockIdx.z;

    const __nv_bfloat16* Abase = (MODE == 0) ? g_wq : g_wp;       // [2][MROWS][CH]
    const __nv_bfloat16* Bbase = g_xb + (size_t)b * 2 * CH * HW;  // [2][CH][HW]
    float* outb = ((MODE == 0) ? (float*)g_qkv : out_p)
                  + ((size_t)b * MROWS + m0) * HW + n0;

    auto issue = [&](int j, int s) {
        const int term = j / 6, kc = j % 6;
        const int sa = (term == 2) ? 1 : 0;       // A split (lo only in term 2)
        const int sb = (term == 1) ? 1 : 0;       // B split (lo only in term 1)
        const __nv_bfloat16* As = Abase + ((size_t)sa * MROWS + m0) * CH + kc * GBK;
        const __nv_bfloat16* Bs = Bbase + ((size_t)sb * CH + kc * GBK) * HW + n0;
#pragma unroll
        for (int u = t; u < 384; u += 192) {      // A: 96 rows x 4 x 16B
            const int r = u >> 2, c = (u & 3) * 8;
            cp16s(smem_u32(&a_s[s][r * ASTR + c]), As + (size_t)r * CH + c);
        }
        for (int u = t; u < 512; u += 192) {      // B: 32 rows x 16 x 16B
            const int r = u >> 4, c = (u & 15) * 8;
            cp16s(smem_u32(&b_s[s][r * BSTR + c]), Bs + (size_t)r * HW + c);
        }
        asm volatile("cp.async.commit_group;");
    };

    const int w  = t >> 5;
    const int wm = w >> 1;     // 0..2
    const int wn = w & 1;      // 0..1

    wmma::fragment<wmma::accumulator, 16, 16, 16, float> acc[2][4];
#pragma unroll
    for (int mi = 0; mi < 2; ++mi)
#pragma unroll
        for (int ni = 0; ni < 4; ++ni) wmma::fill_fragment(acc[mi][ni], 0.f);

    issue(0, 0);
    for (int j = 0; j < 18; ++j) {
        if (j + 1 < 18) {
            issue(j + 1, (j + 1) & 1);
            asm volatile("cp.async.wait_group 1;");
        } else {
            asm volatile("cp.async.wait_group 0;");
        }
        __syncthreads();

        const int s = j & 1;
#pragma unroll
        for (int kk = 0; kk < 2; ++kk) {
            wmma::fragment<wmma::matrix_a, 16, 16, 16, __nv_bfloat16, wmma::row_major> af[2];
            wmma::fragment<wmma::matrix_b, 16, 16, 16, __nv_bfloat16, wmma::row_major> bf[4];
#pragma unroll
            for (int mi = 0; mi < 2; ++mi)
                wmma::load_matrix_sync(af[mi], &a_s[s][(wm * 32 + mi * 16) * ASTR + kk * 16], ASTR);
#pragma unroll
            for (int ni = 0; ni < 4; ++ni)
                wmma::load_matrix_sync(bf[ni], &b_s[s][(kk * 16) * BSTR + wn * 64 + ni * 16], BSTR);
#pragma unroll
            for (int mi = 0; mi < 2; ++mi)
#pragma unroll
                for (int ni = 0; ni < 4; ++ni)
                    wmma::mma_sync(acc[mi][ni], af[mi], bf[ni], acc[mi][ni]);
        }
        __syncthreads();
    }

#pragma unroll
    for (int mi = 0; mi < 2; ++mi)
#pragma unroll
        for (int ni = 0; ni < 4; ++ni)
            wmma::store_matrix_sync(outb + (size_t)(wm * 32 + mi * 16) * HW + wn * 64 + ni * 16,
                                    acc[mi][ni], HW, wmma::mem_row_major);
}

// ---------------------------------------------------------------------------
// E: proj bias add: out[b][o][p] += bias[o]
// ---------------------------------------------------------------------------
__global__ __launch_bounds__(256) void bias_add(float* __restrict__ out,
                                                const float* __restrict__ bp)
{
    const size_t q = (size_t)blockIdx.x * 256 + threadIdx.x;
    if (q >= (size_t)BATCH * CH * HW / 4) return;
    const int o = (int)((q * 4 / HW) % CH);
    const float bb = bp[o];
    float4 v = ((float4*)out)[q];
    v.x += bb; v.y += bb; v.z += bb; v.w += bb;
    ((float4*)out)[q] = v;
}

// ---------------------------------------------------------------------------
// C: attention per (window, head) — round-9 frozen; qkv bias folded into load.
// ---------------------------------------------------------------------------
__global__ __launch_bounds__(192)
void attn_kernel(const float* __restrict__ b_qkv,
                 const float* __restrict__ w_dw,
                 const float* __restrict__ b_dw,
                 const float* __restrict__ temperature)
{
    __shared__ float q_s[HC * CSTR];
    __shared__ float k_s[HC * CSTR + 4];
    __shared__ float v_s[HC * CSTR];
    __shared__ float at [NPIX * CSTR];
    __shared__ float invq[NPIX], invk[NPIX];

    const int win = blockIdx.x;
    const int h   = blockIdx.y;
    const int t   = threadIdx.x;
    const int b  = win >> 10;
    const int wh = (win >> 5) & 31;
    const int ww = win & 31;

    // ---- phase 0: coalesced load + qkv bias ----
    {
        const size_t gbase = (size_t)b * OQ * HW + (size_t)(wh * 7) * IMG + ww * 7;
#pragma unroll
        for (int it = 0; it < 25; ++it) {
            const int u = t + it * 192;
            if (u < 96 * NPIX) {
                const int c = u / NPIX, p = u % NPIX;
                const int sel = c >> 5, cc = c & 31;
                const int ch = sel * CH + h * HC + cc;
                const float v = __ldg(&g_qkv[gbase + (size_t)ch * HW + (p / 7) * IMG + p % 7])
                                + __ldg(&b_qkv[ch]);
                float* dstp = (sel == 0) ? q_s : (sel == 1) ? k_s : v_s;
                dstp[cc * CSTR + p] = v;
            }
        }
    }
    __syncthreads();

    // ---- phase 1: dwconv 3x3 in place ----
    {
        const int c    = t >> 1;
        const int half = t & 1;
        const int sel  = c >> 5;
        const int cc   = c & 31;
        const int ch   = sel * CH + h * HC + cc;
        float* dstp = (sel == 0) ? q_s : (sel == 1) ? k_s : v_s;
        float* row0 = dstp + cc * CSTR;

        float w9[9];
#pragma unroll
        for (int k = 0; k < 9; ++k) w9[k] = w_dw[ch * 9 + k];
        const float bb = b_dw[ch];

        float in[5][7];
        const int r0 = half ? 3 : 0;
        const int nr = half ? 4 : 5;
        for (int r = 0; r < nr; ++r)
#pragma unroll
            for (int j = 0; j < 7; ++j) in[r][j] = row0[(r0 + r) * 7 + j];
        __syncthreads();

        if (!half) {
#pragma unroll
            for (int i = 0; i < 4; ++i) {
#pragma unroll
                for (int j = 0; j < 7; ++j) {
                    float s = bb;
#pragma unroll
                    for (int di = -1; di <= 1; ++di) {
                        const int ii = i + di;
                        if (ii < 0) continue;
#pragma unroll
                        for (int dj = -1; dj <= 1; ++dj) {
                            const int jj = j + dj;
                            if (jj >= 0 && jj < 7)
                                s += w9[(di + 1) * 3 + (dj + 1)] * in[ii][jj];
                        }
                    }
                    row0[i * 7 + j] = s;
                }
            }
        } else {
#pragma unroll
            for (int i = 4; i < 7; ++i) {
#pragma unroll
                for (int j = 0; j < 7; ++j) {
                    float s = bb;
#pragma unroll
                    for (int di = -1; di <= 1; ++di) {
                        const int ii = i + di;
                        if (ii > 6) continue;
#pragma unroll
                        for (int dj = -1; dj <= 1; ++dj) {
                            const int jj = j + dj;
                            if (jj >= 0 && jj < 7)
                                s += w9[(di + 1) * 3 + (dj + 1)] * in[ii - 3][jj];
                        }
                    }
                    row0[i * 7 + j] = s;
                }
            }
        }
    }
    __syncthreads();

    // ---- phase 2: inverse norms ----
    if (t < 2 * NPIX) {
        const int part = t / NPIX, p = t % NPIX;
        const float* s = part ? k_s : q_s;
        float acc = 0.f;
#pragma unroll
        for (int c = 0; c < HC; ++c) { const float v = s[c * CSTR + p]; acc += v * v; }
        const float nm = fmaxf(sqrtf(acc), 1e-12f);
        if (part == 0) invq[p] = temperature[h] / nm;
        else           invk[p] = 1.f / nm;
    }
    __syncthreads();

    // ---- phase 3: KtQ, 4n x 7m tile ----
    if (t < 91) {
        const int n0 = 4 * (t / 7);
        const int m0 = 7 * (t % 7);
        float a0[7], a1[7], a2[7], a3[7];
#pragma unroll
        for (int jm = 0; jm < 7; ++jm) { a0[jm] = a1[jm] = a2[jm] = a3[jm] = 0.f; }
#pragma unroll
        for (int c = 0; c < HC; ++c) {
            const float2 ka = *(const float2*)&k_s[c * CSTR + n0];
            const float2 kb = *(const float2*)&k_s[c * CSTR + n0 + 2];
#pragma unroll
            for (int jm = 0; jm < 7; ++jm) {
                const float qv = q_s[c * CSTR + m0 + jm];
                a0[jm] += ka.x * qv;
                a1[jm] += ka.y * qv;
                a2[jm] += kb.x * qv;
                a3[jm] += kb.y * qv;
            }
        }
        const float ik0 = invk[n0];
#pragma unroll
        for (int jm = 0; jm < 7; ++jm)
            at[n0 * CSTR + m0 + jm] = a0[jm] * ik0 * invq[m0 + jm];
        if (n0 + 1 < NPIX) {
            const float ik1 = invk[n0 + 1];
            const float ik2 = invk[n0 + 2];
            const float ik3 = invk[n0 + 3];
#pragma unroll
            for (int jm = 0; jm < 7; ++jm) {
                const float iq = invq[m0 + jm];
                at[(n0 + 1) * CSTR + m0 + jm] = a1[jm] * ik1 * iq;
                at[(n0 + 2) * CSTR + m0 + jm] = a2[jm] * ik2 * iq;
                at[(n0 + 3) * CSTR + m0 + jm] = a3[jm] * ik3 * iq;
            }
        }
    }
    __syncthreads();

    // ---- phase 4: softmax over n (2 threads/col + shfl) ----
    {
        const int m = (t < 98) ? (t >> 1) : 0;
        const int part = t & 1;
        float mx = -1e30f;
        for (int n = part; n < NPIX; n += 2) mx = fmaxf(mx, at[n * CSTR + m]);
        mx = fmaxf(mx, __shfl_xor_sync(0xffffffffu, mx, 1));
        float ev[25];
        float ssum = 0.f;
        int cnt = 0;
        for (int n = part; n < NPIX; n += 2) {
            const float e = __expf(at[n * CSTR + m] - mx);
            ev[cnt++] = e;
            ssum += e;
        }
        ssum += __shfl_xor_sync(0xffffffffu, ssum, 1);
        const float r = 1.f / ssum;
        __syncthreads();
        if (t < 98) {
            cnt = 0;
            for (int n = part; n < NPIX; n += 2) at[n * CSTR + m] = ev[cnt++] * r;
        }
    }
    __syncthreads();

    // ---- phase 5: V*attn, 2c x 7m tile ----
    if (t < 112) {
        const int c0 = 2 * (t / 7), mg = t % 7;
        const int m0 = 7 * mg;
        float a0[7], a1[7];
#pragma unroll
        for (int jm = 0; jm < 7; ++jm) { a0[jm] = 0.f; a1[jm] = 0.f; }
#pragma unroll 4
        for (int n = 0; n < 48; n += 2) {
            const float2 v0 = *(const float2*)&v_s[c0 * CSTR + n];
            const float2 v1 = *(const float2*)&v_s[(c0 + 1) * CSTR + n];
#pragma unroll
            for (int jm = 0; jm < 7; ++jm) {
                const float at0 = at[n * CSTR + m0 + jm];
                const float at1 = at[(n + 1) * CSTR + m0 + jm];
                a0[jm] += v0.x * at0 + v0.y * at1;
                a1[jm] += v1.x * at0 + v1.y * at1;
            }
        }
        const float v48_0 = v_s[c0 * CSTR + 48];
        const float v48_1 = v_s[(c0 + 1) * CSTR + 48];
#pragma unroll
        for (int jm = 0; jm < 7; ++jm) {
            const float at48 = at[48 * CSTR + m0 + jm];
            a0[jm] += v48_0 * at48;
            a1[jm] += v48_1 * at48;
        }

        float* dst = g_attn + (((size_t)(b * CH + h * HC + c0) * IMG) + wh * 7 + mg) * IMG + ww * 7;
#pragma unroll
        for (int jm = 0; jm < 7; ++jm) dst[jm] = a0[jm];
        dst += (size_t)IMG * IMG;
#pragma unroll
        for (int jm = 0; jm < 7; ++jm) dst[jm] = a1[jm];
    }
}

// ---------------------------------------------------------------------------
extern "C" void kernel_launch(void* const* d_in, const int* in_sizes, int n_in,
                              void* d_out, int out_size)
{
    const float* x      = (const float*)d_in[0];
    const float* w_qkv  = (const float*)d_in[1];
    const float* b_qkv  = (const float*)d_in[2];
    const float* w_dw   = (const float*)d_in[3];
    const float* b_dw   = (const float*)d_in[4];
    const float* w_proj = (const float*)d_in[5];
    const float* b_proj = (const float*)d_in[6];
    const float* temp   = (const float*)d_in[7];
    float* out = (float*)d_out;

    const int XQ = (int)(((size_t)BATCH * CH * HW / 4 + 255) / 256);

    // W: weights -> bf16 hi/lo
    wprep<<<(OQ * CH + CH * CH + 255) / 256, 256>>>(w_qkv, w_proj);
    // X: x -> bf16 hi/lo planar
    xprep<0><<<XQ, 256>>>(x);
    // A: QKV GEMM (WMMA bf16x3) -> g_qkv
    gemm_wmma<OQ, 0><<<dim3(HW / GBN, OQ / GBM, BATCH), 192>>>(nullptr);
    // C: attention (qkv bias folded) -> g_attn
    attn_kernel<<<dim3(NW, HEADS), 192>>>(b_qkv, w_dw, b_dw, temp);
    // X2: g_attn -> bf16 hi/lo planar
    xprep<1><<<XQ, 256>>>(nullptr);
    // D: proj GEMM (WMMA bf16x3) -> out
    gemm_wmma<CH, 1><<<dim3(HW / GBN, CH / GBM, BATCH), 192>>>(out);
    // E: proj bias
    bias_add<<<XQ, 256>>>(out, b_proj);
}